// round 7
// baseline (speedup 1.0000x reference)
#include <cuda_runtime.h>
#include <cuda_bf16.h>
#include <cstdint>

#define SEQ 2048
#define NROWS 4096
#define HID 1024
#define GC 1536   // global proj cols: Q 0, K 512, V 1024
#define LC 2560   // local proj cols: LQ 0, LK1 512, LK2 1024, LV1 1536, LV2 2048

__device__ __nv_bfloat16 g_Xh[(size_t)NROWS * HID];
__device__ __nv_bfloat16 g_Xl[(size_t)NROWS * HID];
__device__ __nv_bfloat16 g_Wth[(size_t)4096 * HID];   // all 8 W, transposed [n][k]
__device__ __nv_bfloat16 g_Wtl[(size_t)4096 * HID];
__device__ float g_bias[4096];
__device__ __nv_bfloat16 g_Pg[(size_t)NROWS * GC];    // global projections bf16
__device__ float g_Pf[(size_t)NROWS * LC];            // local projections fp32
__device__ float g_Mpart[8 * 16 * 64 * 64];
__device__ float g_M[16 * 64 * 64];
// precomputed flash_local operand planes (bf16 hi/lo)
__device__ __nv_bfloat16 g_K2h[(size_t)NROWS * 512];
__device__ __nv_bfloat16 g_K2l[(size_t)NROWS * 512];
__device__ __nv_bfloat16 g_Vmh[(size_t)NROWS * 512];
__device__ __nv_bfloat16 g_Vml[(size_t)NROWS * 512];

struct ProjArgs { const float* w[8]; const float* b[8]; };

// ---------------- helpers ----------------
__device__ __forceinline__ uint32_t cvta_s(const void* p) {
    return (uint32_t)__cvta_generic_to_shared(p);
}
__device__ __forceinline__ void cp16(void* smem, const void* gmem) {
    asm volatile("cp.async.cg.shared.global [%0], [%1], 16;"
                 :: "r"(cvta_s(smem)), "l"(gmem));
}
__device__ __forceinline__ void ldsm_x4(uint32_t r[4], uint32_t a) {
    asm volatile("ldmatrix.sync.aligned.m8n8.x4.shared.b16 {%0,%1,%2,%3}, [%4];"
                 : "=r"(r[0]), "=r"(r[1]), "=r"(r[2]), "=r"(r[3]) : "r"(a));
}
__device__ __forceinline__ void ldsm_x4t(uint32_t r[4], uint32_t a) {
    asm volatile("ldmatrix.sync.aligned.m8n8.x4.trans.shared.b16 {%0,%1,%2,%3}, [%4];"
                 : "=r"(r[0]), "=r"(r[1]), "=r"(r[2]), "=r"(r[3]) : "r"(a));
}
__device__ __forceinline__ void mma_bf16(float c[4], const uint32_t a[4], const uint32_t b[2]) {
    asm volatile("mma.sync.aligned.m16n8k16.row.col.f32.bf16.bf16.f32 "
                 "{%0,%1,%2,%3},{%4,%5,%6,%7},{%8,%9},{%0,%1,%2,%3};"
                 : "+f"(c[0]), "+f"(c[1]), "+f"(c[2]), "+f"(c[3])
                 : "r"(a[0]), "r"(a[1]), "r"(a[2]), "r"(a[3]), "r"(b[0]), "r"(b[1]));
}
__device__ __forceinline__ void mma_bf16b(float c[4], const uint32_t a[4], uint32_t b0, uint32_t b1) {
    asm volatile("mma.sync.aligned.m16n8k16.row.col.f32.bf16.bf16.f32 "
                 "{%0,%1,%2,%3},{%4,%5,%6,%7},{%8,%9},{%0,%1,%2,%3};"
                 : "+f"(c[0]), "+f"(c[1]), "+f"(c[2]), "+f"(c[3])
                 : "r"(a[0]), "r"(a[1]), "r"(a[2]), "r"(a[3]), "r"(b0), "r"(b1));
}
__device__ __forceinline__ void split2(float x, __nv_bfloat16& h, __nv_bfloat16& l) {
    h = __float2bfloat16_rn(x);
    l = __float2bfloat16_rn(x - __bfloat162float(h));
}
__device__ __forceinline__ uint32_t pack_bf16(float a, float b) {
    __nv_bfloat162 t = __floats2bfloat162_rn(a, b);
    return *(uint32_t*)&t;
}
__device__ __forceinline__ void pack_hl(float a, float b, uint32_t& h, uint32_t& l) {
    __nv_bfloat162 hh = __floats2bfloat162_rn(a, b);
    __nv_bfloat162 ll = __floats2bfloat162_rn(a - __bfloat162float(hh.x),
                                              b - __bfloat162float(hh.y));
    h = *(uint32_t*)&hh; l = *(uint32_t*)&ll;
}

// ---------------- prep kernels ----------------
__global__ void split_X(const float* __restrict__ X) {
    int t = blockIdx.x * 256 + threadIdx.x;
    float4 v = *(const float4*)&X[(size_t)t * 4];
    __nv_bfloat16 h, l;
    split2(v.x, h, l); g_Xh[(size_t)t*4+0] = h; g_Xl[(size_t)t*4+0] = l;
    split2(v.y, h, l); g_Xh[(size_t)t*4+1] = h; g_Xl[(size_t)t*4+1] = l;
    split2(v.z, h, l); g_Xh[(size_t)t*4+2] = h; g_Xl[(size_t)t*4+2] = l;
    split2(v.w, h, l); g_Xh[(size_t)t*4+3] = h; g_Xl[(size_t)t*4+3] = l;
}

__global__ void transW(ProjArgs pa) {
    __shared__ float tile[32][33];
    const int nb = blockIdx.x, kb = blockIdx.y, w = blockIdx.z;
    const float* __restrict__ W = pa.w[w];
    const int tx = threadIdx.x & 31, ty0 = threadIdx.x >> 5;
#pragma unroll
    for (int i = 0; i < 4; i++) {
        int ty = ty0 + 8 * i;
        tile[ty][tx] = W[(size_t)(kb * 32 + ty) * 512 + nb * 32 + tx];
    }
    __syncthreads();
#pragma unroll
    for (int i = 0; i < 4; i++) {
        int ty = ty0 + 8 * i;
        __nv_bfloat16 h, l; split2(tile[tx][ty], h, l);
        size_t o = (size_t)(w * 512 + nb * 32 + ty) * HID + kb * 32 + tx;
        g_Wth[o] = h; g_Wtl[o] = l;
    }
}

__global__ void bias_cat(ProjArgs pa) {
    int t = blockIdx.x * 256 + threadIdx.x;
    g_bias[t] = pa.b[t >> 9][t & 511];
}

// prep for flash_local: bf16 hi/lo LK2 planes + bf16 hi/lo merged-V planes
__global__ void prep_local() {
    int t = blockIdx.x * 256 + threadIdx.x;      // 4096*128
    int r = t >> 7, c4 = (t & 127) * 4;
    size_t grow = (size_t)r * LC;
    size_t po = (size_t)r * 512 + c4;
    float4 k = *(const float4*)&g_Pf[grow + 1024 + c4];
    __nv_bfloat162 h01, h23, l01, l23;
    split2(k.x, h01.x, l01.x); split2(k.y, h01.y, l01.y);
    split2(k.z, h23.x, l23.x); split2(k.w, h23.y, l23.y);
    *(__nv_bfloat162*)&g_K2h[po]     = h01;
    *(__nv_bfloat162*)&g_K2h[po + 2] = h23;
    *(__nv_bfloat162*)&g_K2l[po]     = l01;
    *(__nv_bfloat162*)&g_K2l[po + 2] = l23;
    float4 v1 = *(const float4*)&g_Pf[grow + 1536 + c4];
    float4 v2 = *(const float4*)&g_Pf[grow + 2048 + c4];
    split2(v1.x + v2.x, h01.x, l01.x); split2(v1.y + v2.y, h01.y, l01.y);
    split2(v1.z + v2.z, h23.x, l23.x); split2(v1.w + v2.w, h23.y, l23.y);
    *(__nv_bfloat162*)&g_Vmh[po]     = h01;
    *(__nv_bfloat162*)&g_Vmh[po + 2] = h23;
    *(__nv_bfloat162*)&g_Vml[po]     = l01;
    *(__nv_bfloat162*)&g_Vml[po + 2] = l23;
}

// ---------------- global projection GEMM (1-term, 3-stage pipeline) ----------------
__global__ __launch_bounds__(256, 2) void proj_g() {
    extern __shared__ char psg[];
    __nv_bfloat16* SB = (__nv_bfloat16*)psg;
    float* sbias = (float*)(psg + 61440);
    const int bm = blockIdx.y, bn = blockIdx.x;        // bn 0..11
    const int tid = threadIdx.x, lane = tid & 31, warp = tid >> 5;
    const int wr = warp >> 1, wc = warp & 1;
    const int g = lane >> 2, tig = lane & 3;
    if (tid < 128) sbias[tid] = g_bias[bn * 128 + tid];
    const int lr = tid >> 2, lch = tid & 3;

#define GP_A(s) (SB + (s) * 5120)
#define GP_B(s) (SB + 15360 + (s) * 5120)
#define GP_ISS(kt, s) {                                                        \
        int k0 = (kt) * 32;                                                    \
        size_t ga0 = (size_t)(bm * 128 + lr) * HID + k0 + lch * 8;             \
        size_t gb0 = (size_t)(bn * 128 + lr) * HID + k0 + lch * 8;             \
        cp16(GP_A(s) + lr * 40 + lch * 8,        g_Xh + ga0);                  \
        cp16(GP_A(s) + (lr + 64) * 40 + lch * 8, g_Xh + ga0 + 64 * HID);       \
        cp16(GP_B(s) + lr * 40 + lch * 8,        g_Wth + gb0);                 \
        cp16(GP_B(s) + (lr + 64) * 40 + lch * 8, g_Wth + gb0 + 64 * HID); }

    float c[2][8][4];
#pragma unroll
    for (int mf = 0; mf < 2; mf++)
#pragma unroll
        for (int nf = 0; nf < 8; nf++)
#pragma unroll
            for (int i = 0; i < 4; i++) c[mf][nf][i] = 0.f;

    GP_ISS(0, 0); asm volatile("cp.async.commit_group;");
    GP_ISS(1, 1); asm volatile("cp.async.commit_group;");

    for (int kt = 0; kt < 32; kt++) {
        const int s = kt % 3;
        asm volatile("cp.async.wait_group 1;");
        __syncthreads();
        if (kt + 2 < 32) { GP_ISS(kt + 2, (kt + 2) % 3); }
        asm volatile("cp.async.commit_group;");

        __nv_bfloat16* Ah = GP_A(s);
        __nv_bfloat16* Bh = GP_B(s);
        uint32_t ah[2][2][4];
#pragma unroll
        for (int mf = 0; mf < 2; mf++)
#pragma unroll
            for (int ks = 0; ks < 2; ks++) {
                int row = wr * 32 + mf * 16 + (lane & 15);
                int col = ks * 16 + (lane >> 4) * 8;
                ldsm_x4(ah[mf][ks], cvta_s(&Ah[row * 40 + col]));
            }
#pragma unroll
        for (int nfp = 0; nfp < 4; nfp++) {
#pragma unroll
            for (int ks = 0; ks < 2; ks++) {
                uint32_t b4[4];
                int row = wc * 64 + nfp * 16 + (lane & 15);
                int col = ks * 16 + (lane >> 4) * 8;
                ldsm_x4(b4, cvta_s(&Bh[row * 40 + col]));
#pragma unroll
                for (int mf = 0; mf < 2; mf++) {
                    mma_bf16b(c[mf][2 * nfp],     ah[mf][ks], b4[0], b4[2]);
                    mma_bf16b(c[mf][2 * nfp + 1], ah[mf][ks], b4[1], b4[3]);
                }
            }
        }
    }

#pragma unroll
    for (int mf = 0; mf < 2; mf++)
#pragma unroll
        for (int nf = 0; nf < 8; nf++) {
            int lcol = wc * 64 + nf * 8 + 2 * tig;
            int gcol = bn * 128 + lcol;
            int r0 = bm * 128 + wr * 32 + mf * 16 + g;
            float v0 = c[mf][nf][0] + sbias[lcol];
            float v1 = c[mf][nf][1] + sbias[lcol + 1];
            float v2 = c[mf][nf][2] + sbias[lcol];
            float v3 = c[mf][nf][3] + sbias[lcol + 1];
            *(uint32_t*)&g_Pg[(size_t)r0 * GC + gcol]       = pack_bf16(v0, v1);
            *(uint32_t*)&g_Pg[(size_t)(r0 + 8) * GC + gcol] = pack_bf16(v2, v3);
        }
}

// ---------------- local projection GEMM (3-term, 3-stage pipeline) ----------------
__global__ __launch_bounds__(256) void proj_l() {
    extern __shared__ char psl[];
    __nv_bfloat16* SB = (__nv_bfloat16*)psl;   // 3 stages x 4 planes x 5120 bf16
    float* sbias = (float*)(psl + 122880);
    const int bm = blockIdx.y, bn = blockIdx.x;        // bn 0..19
    const int tid = threadIdx.x, lane = tid & 31, warp = tid >> 5;
    const int wr = warp >> 1, wc = warp & 1;
    const int g = lane >> 2, tig = lane & 3;
    if (tid < 128) sbias[tid] = g_bias[GC + bn * 128 + tid];
    const int lr = tid >> 2, lch = tid & 3;

#define LP_AH(s) (SB + (s) * 20480)
#define LP_BH(s) (SB + (s) * 20480 + 5120)
#define LP_AL(s) (SB + (s) * 20480 + 10240)
#define LP_BL(s) (SB + (s) * 20480 + 15360)
#define LP_ISS(kt, s) {                                                        \
        int k0 = (kt) * 32;                                                    \
        size_t ga0 = (size_t)(bm * 128 + lr) * HID + k0 + lch * 8;             \
        size_t gb0 = (size_t)(GC + bn * 128 + lr) * HID + k0 + lch * 8;        \
        cp16(LP_AH(s) + lr * 40 + lch * 8,        g_Xh + ga0);                 \
        cp16(LP_AH(s) + (lr + 64) * 40 + lch * 8, g_Xh + ga0 + 64 * HID);      \
        cp16(LP_BH(s) + lr * 40 + lch * 8,        g_Wth + gb0);                \
        cp16(LP_BH(s) + (lr + 64) * 40 + lch * 8, g_Wth + gb0 + 64 * HID);     \
        cp16(LP_AL(s) + lr * 40 + lch * 8,        g_Xl + ga0);                 \
        cp16(LP_AL(s) + (lr + 64) * 40 + lch * 8, g_Xl + ga0 + 64 * HID);      \
        cp16(LP_BL(s) + lr * 40 + lch * 8,        g_Wtl + gb0);                \
        cp16(LP_BL(s) + (lr + 64) * 40 + lch * 8, g_Wtl + gb0 + 64 * HID); }

    float c[2][8][4];
#pragma unroll
    for (int mf = 0; mf < 2; mf++)
#pragma unroll
        for (int nf = 0; nf < 8; nf++)
#pragma unroll
            for (int i = 0; i < 4; i++) c[mf][nf][i] = 0.f;

    LP_ISS(0, 0); asm volatile("cp.async.commit_group;");
    LP_ISS(1, 1); asm volatile("cp.async.commit_group;");

    for (int kt = 0; kt < 32; kt++) {
        const int s = kt % 3;
        asm volatile("cp.async.wait_group 1;");
        __syncthreads();
        if (kt + 2 < 32) { LP_ISS(kt + 2, (kt + 2) % 3); }
        asm volatile("cp.async.commit_group;");

        __nv_bfloat16* Ah = LP_AH(s);
        __nv_bfloat16* Bh = LP_BH(s);
        __nv_bfloat16* Al = LP_AL(s);
        __nv_bfloat16* Bl = LP_BL(s);
        uint32_t ah[2][2][4], al[2][2][4];
#pragma unroll
        for (int mf = 0; mf < 2; mf++)
#pragma unroll
            for (int ks = 0; ks < 2; ks++) {
                int row = wr * 32 + mf * 16 + (lane & 15);
                int col = ks * 16 + (lane >> 4) * 8;
                ldsm_x4(ah[mf][ks], cvta_s(&Ah[row * 40 + col]));
                ldsm_x4(al[mf][ks], cvta_s(&Al[row * 40 + col]));
            }
#pragma unroll
        for (int nfp = 0; nfp < 4; nfp++) {
#pragma unroll
            for (int ks = 0; ks < 2; ks++) {
                uint32_t bh4[4], bl4[4];
                int row = wc * 64 + nfp * 16 + (lane & 15);
                int col = ks * 16 + (lane >> 4) * 8;
                ldsm_x4(bh4, cvta_s(&Bh[row * 40 + col]));
                ldsm_x4(bl4, cvta_s(&Bl[row * 40 + col]));
#pragma unroll
                for (int mf = 0; mf < 2; mf++) {
                    mma_bf16b(c[mf][2 * nfp],     ah[mf][ks], bh4[0], bh4[2]);
                    mma_bf16b(c[mf][2 * nfp],     al[mf][ks], bh4[0], bh4[2]);
                    mma_bf16b(c[mf][2 * nfp],     ah[mf][ks], bl4[0], bl4[2]);
                    mma_bf16b(c[mf][2 * nfp + 1], ah[mf][ks], bh4[1], bh4[3]);
                    mma_bf16b(c[mf][2 * nfp + 1], al[mf][ks], bh4[1], bh4[3]);
                    mma_bf16b(c[mf][2 * nfp + 1], ah[mf][ks], bl4[1], bl4[3]);
                }
            }
        }
    }

#pragma unroll
    for (int mf = 0; mf < 2; mf++)
#pragma unroll
        for (int nf = 0; nf < 8; nf++) {
            int lcol = wc * 64 + nf * 8 + 2 * tig;
            int fc = bn * 128 + lcol;
            int r0 = bm * 128 + wr * 32 + mf * 16 + g;
            g_Pf[(size_t)r0 * LC + fc]           = c[mf][nf][0] + sbias[lcol];
            g_Pf[(size_t)r0 * LC + fc + 1]       = c[mf][nf][1] + sbias[lcol + 1];
            g_Pf[(size_t)(r0 + 8) * LC + fc]     = c[mf][nf][2] + sbias[lcol];
            g_Pf[(size_t)(r0 + 8) * LC + fc + 1] = c[mf][nf][3] + sbias[lcol + 1];
        }
}

// ---------------- M = lk1^T lk1 (fp32) ----------------
__global__ __launch_bounds__(256) void compute_M_part() {
    __shared__ float Ls[64 * 68];
    const int bh = blockIdx.x, b = bh >> 3, h = bh & 7;
    const int part = blockIdx.y;
    const int tid = threadIdx.x, e = tid & 63, d0 = tid >> 6;
    float acc[16];
#pragma unroll
    for (int i = 0; i < 16; i++) acc[i] = 0.f;
    const int colbase = 512 + h * 64;
    for (int t = 0; t < 4; t++) {
        const int s0 = (part * 4 + t) * 64;
        __syncthreads();
#pragma unroll
        for (int ch = 0; ch < 4; ch++) {
            int idx = tid + 256 * ch;
            int r = idx >> 4, c4 = (idx & 15) * 4;
            *(float4*)&Ls[r * 68 + c4] =
                *(const float4*)&g_Pf[(size_t)(b * SEQ + s0 + r) * LC + colbase + c4];
        }
        __syncthreads();
        for (int r = 0; r < 64; r++) {
            float le = Ls[r * 68 + e];
#pragma unroll
            for (int i = 0; i < 16; i++)
                acc[i] += Ls[r * 68 + d0 + 4 * i] * le;
        }
    }
#pragma unroll
    for (int i = 0; i < 16; i++)
        g_Mpart[((size_t)part * 16 + bh) * 4096 + (d0 + 4 * i) * 64 + e] = acc[i];
}

__global__ __launch_bounds__(256) void reduce_M() {
    const int t = blockIdx.x * 256 + threadIdx.x;
    const int bh = t >> 12, idx = t & 4095;
    float s = 0.f;
#pragma unroll
    for (int p = 0; p < 8; p++) s += g_Mpart[((size_t)p * 16 + bh) * 4096 + idx];
    g_M[(size_t)bh * 4096 + idx] = s;
}

// ---------------- LQ' = LQ @ M (fp32, in place) ----------------
__global__ __launch_bounds__(256) void lq_update() {
    __shared__ float Ms[64 * 65];
    __shared__ float Ls[64 * 68];
    const int rb = blockIdx.x, h = blockIdx.y;
    const int row0 = rb * 64, b = row0 >> 11, bh = b * 8 + h;
    const int tid = threadIdx.x;
    const int colbase = h * 64;
#pragma unroll
    for (int ch = 0; ch < 16; ch++) {
        int idx = tid + 256 * ch;
        Ms[(idx >> 6) * 65 + (idx & 63)] = g_M[(size_t)bh * 4096 + idx];
    }
#pragma unroll
    for (int ch = 0; ch < 4; ch++) {
        int idx = tid + 256 * ch;
        int r = idx >> 4, c4 = (idx & 15) * 4;
        *(float4*)&Ls[r * 68 + c4] =
            *(const float4*)&g_Pf[(size_t)(row0 + r) * LC + colbase + c4];
    }
    __syncthreads();
    const int e = tid & 63, r0 = tid >> 6;
    float acc[16];
#pragma unroll
    for (int i = 0; i < 16; i++) acc[i] = 0.f;
    for (int d = 0; d < 64; d++) {
        float mv = Ms[d * 65 + e];
#pragma unroll
        for (int i = 0; i < 16; i++)
            acc[i] += Ls[(r0 + 4 * i) * 68 + d] * mv;
    }
#pragma unroll
    for (int i = 0; i < 16; i++)
        g_Pf[(size_t)(row0 + r0 + 4 * i) * LC + colbase + e] = acc[i];
}

// ---------------- global flash: BM=128, 3-stage pipeline, 2 CTAs/SM ----------------
__global__ __launch_bounds__(256, 2) void flash_global(const float* __restrict__ mask,
                                                       float* __restrict__ out) {
    extern __shared__ char gsm[];
    __nv_bfloat16* Qs = (__nv_bfloat16*)gsm;                 // 128*72
    float* maskS = (float*)(gsm + 18432);                    // 2048 floats
#define GF_K(s) ((__nv_bfloat16*)(gsm + 26624 + (s) * 18432))
#define GF_V(s) ((__nv_bfloat16*)(gsm + 26624 + (s) * 18432 + 9216))
    const int tid = threadIdx.x, lane = tid & 31, warp = tid >> 5;
    const int g = lane >> 2, tig = lane & 3;
    const int qb = blockIdx.x, by = blockIdx.y;
    const int b = by >> 3, h = by & 7;
    const int qcol = h * 64, kcol = 512 + h * 64, vcol = 1024 + h * 64;
    const int rowbase = b * SEQ;
    const int lr = tid >> 2, lch = tid & 3;

#define GF_ISS(kt, s) {                                                        \
        size_t grow = (size_t)(rowbase + (kt) * 64 + lr) * GC;                 \
        cp16(GF_K(s) + lr * 72 + lch * 16,     &g_Pg[grow + kcol + lch * 16]); \
        cp16(GF_K(s) + lr * 72 + lch * 16 + 8, &g_Pg[grow + kcol + lch * 16 + 8]); \
        cp16(GF_V(s) + lr * 72 + lch * 16,     &g_Pg[grow + vcol + lch * 16]); \
        cp16(GF_V(s) + lr * 72 + lch * 16 + 8, &g_Pg[grow + vcol + lch * 16 + 8]); }

#pragma unroll
    for (int i = 0; i < 8; i++) maskS[tid + 256 * i] = mask[b * SEQ + tid + 256 * i];
#pragma unroll
    for (int i = 0; i < 4; i++) {
        int idx = tid + 256 * i;
        int r = idx >> 3, ch = idx & 7;
        *(uint4*)&Qs[r * 72 + ch * 8] =
            *(const uint4*)&g_Pg[(size_t)(rowbase + qb * 128 + r) * GC + qcol + ch * 8];
    }
    GF_ISS(0, 0); asm volatile("cp.async.commit_group;");
    GF_ISS(1, 1); asm volatile("cp.async.commit_group;");
    __syncthreads();

    uint32_t qf[4][4];
#pragma unroll
    for (int ks = 0; ks < 4; ks++) {
        int row = warp * 16 + (lane & 15);
        int col = ks * 16 + (lane >> 4) * 8;
        ldsm_x4(qf[ks], cvta_s(&Qs[row * 72 + col]));
    }

    float of[8][4];
#pragma unroll
    for (int nf = 0; nf < 8; nf++)
#pragma unroll
        for (int i = 0; i < 4; i++) of[nf][i] = 0.f;
    float m0 = -1e30f, m1 = -1e30f, l0 = 0.f, l1 = 0.f;

    for (int kt = 0; kt < 32; kt++) {
        const int s = kt % 3;
        asm volatile("cp.async.wait_group 1;");
        __syncthreads();
        if (kt + 2 < 32) { GF_ISS(kt + 2, (kt + 2) % 3); }
        asm volatile("cp.async.commit_group;");

        __nv_bfloat16* Ks = GF_K(s);
        __nv_bfloat16* Vs = GF_V(s);

        float sf[8][4];
#pragma unroll
        for (int nfp = 0; nfp < 4; nfp++) {
#pragma unroll
            for (int i = 0; i < 4; i++) { sf[2*nfp][i] = 0.f; sf[2*nfp+1][i] = 0.f; }
#pragma unroll
            for (int ks = 0; ks < 4; ks++) {
                uint32_t k4[4];
                int row = nfp * 16 + (lane & 15);
                int col = ks * 16 + (lane >> 4) * 8;
                ldsm_x4(k4, cvta_s(&Ks[row * 72 + col]));
                mma_bf16b(sf[2 * nfp],     qf[ks], k4[0], k4[2]);
                mma_bf16b(sf[2 * nfp + 1], qf[ks], k4[1], k4[3]);
            }
        }

        float mx0 = -1e30f, mx1 = -1e30f;
#pragma unroll
        for (int nf = 0; nf < 8; nf++) {
            float a0 = maskS[kt * 64 + nf * 8 + 2 * tig];
            float a1 = maskS[kt * 64 + nf * 8 + 2 * tig + 1];
            sf[nf][0] = sf[nf][0] * 0.125f + a0;
            sf[nf][1] = sf[nf][1] * 0.125f + a1;
            sf[nf][2] = sf[nf][2] * 0.125f + a0;
            sf[nf][3] = sf[nf][3] * 0.125f + a1;
            mx0 = fmaxf(mx0, fmaxf(sf[nf][0], sf[nf][1]));
            mx1 = fmaxf(mx1, fmaxf(sf[nf][2], sf[nf][3]));
        }
        mx0 = fmaxf(mx0, __shfl_xor_sync(~0u, mx0, 1));
        mx0 = fmaxf(mx0, __shfl_xor_sync(~0u, mx0, 2));
        mx1 = fmaxf(mx1, __shfl_xor_sync(~0u, mx1, 1));
        mx1 = fmaxf(mx1, __shfl_xor_sync(~0u, mx1, 2));
        float mn0 = fmaxf(m0, mx0), mn1 = fmaxf(m1, mx1);
        float cr0 = __expf(m0 - mn0), cr1 = __expf(m1 - mn1);
        m0 = mn0; m1 = mn1;

        float ps0 = 0.f, ps1 = 0.f;
        uint32_t pa[4][4];
#pragma unroll
        for (int nf = 0; nf < 8; nf++) {
            float p0 = __expf(sf[nf][0] - mn0), p1 = __expf(sf[nf][1] - mn0);
            float p2 = __expf(sf[nf][2] - mn1), p3 = __expf(sf[nf][3] - mn1);
            ps0 += p0 + p1; ps1 += p2 + p3;
            int ks = nf >> 1;
            if (nf & 1) { pa[ks][2] = pack_bf16(p0, p1); pa[ks][3] = pack_bf16(p2, p3); }
            else        { pa[ks][0] = pack_bf16(p0, p1); pa[ks][1] = pack_bf16(p2, p3); }
        }
        ps0 += __shfl_xor_sync(~0u, ps0, 1); ps0 += __shfl_xor_sync(~0u, ps0, 2);
        ps1 += __shfl_xor_sync(~0u, ps1, 1); ps1 += __shfl_xor_sync(~0u, ps1, 2);
        l0 = l0 * cr0 + ps0; l1 = l1 * cr1 + ps1;
#pragma unroll
        for (int nf = 0; nf < 8; nf++) {
            of[nf][0] *= cr0; of[nf][1] *= cr0; of[nf][2] *= cr1; of[nf][3] *= cr1;
        }
#pragma unroll
        for (int nfp = 0; nfp < 4; nfp++)
#pragma unroll
            for (int ks = 0; ks < 4; ks++) {
                uint32_t v4[4];
                int row = ks * 16 + (lane & 15);
                int col = nfp * 16 + (lane >> 4) * 8;
                ldsm_x4t(v4, cvta_s(&Vs[row * 72 + col]));
                mma_bf16b(of[2 * nfp],     pa[ks], v4[0], v4[1]);
                mma_bf16b(of[2 * nfp + 1], pa[ks], v4[2], v4[3]);
            }
    }

    const float inv0 = 1.f / l0, inv1 = 1.f / l1;
    const int r0 = rowbase + qb * 128 + warp * 16 + g;
#pragma unroll
    for (int nf = 0; nf < 8; nf++) {
        int col = h * 64 + nf * 8 + 2 * tig;
        out[(size_t)r0 * HID + col]           = of[nf][0] * inv0;
        out[(size_t)r0 * HID + col + 1]       = of[nf][1] * inv0;
        out[(size_t)(r0 + 8) * HID + col]     = of[nf][2] * inv1;
        out[(size_t)(r0 + 8) * HID + col + 1] = of[nf][3] * inv1;
    }
}

// ---------------- local flash: bf16 3-term QK, 2-term PV, 2 CTAs/SM ----------------
__global__ __launch_bounds__(256, 2) void flash_local(float* __restrict__ out) {
    extern __shared__ char lsm[];
#define LF_KH(s) ((__nv_bfloat16*)(lsm + (s) * 36864))
#define LF_KL(s) ((__nv_bfloat16*)(lsm + (s) * 36864 + 9216))
#define LF_VH(s) ((__nv_bfloat16*)(lsm + (s) * 36864 + 18432))
#define LF_VL(s) ((__nv_bfloat16*)(lsm + (s) * 36864 + 27648))
    const int tid = threadIdx.x, lane = tid & 31, warp = tid >> 5;
    const int g = lane >> 2, tig = lane & 3;
    const int qb = blockIdx.x, by = blockIdx.y;
    const int b = by >> 3, h = by & 7;
    const int rowbase = b * SEQ;
    const int lr = tid >> 2, lch = tid & 3;

#define LF_ISS(kt, s) {                                                        \
        size_t go = (size_t)(rowbase + (kt) * 64 + lr) * 512 + h * 64 + lch * 16; \
        cp16(LF_KH(s) + lr * 72 + lch * 16,     &g_K2h[go]);                   \
        cp16(LF_KH(s) + lr * 72 + lch * 16 + 8, &g_K2h[go + 8]);               \
        cp16(LF_KL(s) + lr * 72 + lch * 16,     &g_K2l[go]);                   \
        cp16(LF_KL(s) + lr * 72 + lch * 16 + 8, &g_K2l[go + 8]);               \
        cp16(LF_VH(s) + lr * 72 + lch * 16,     &g_Vmh[go]);                   \
        cp16(LF_VH(s) + lr * 72 + lch * 16 + 8, &g_Vmh[go + 8]);               \
        cp16(LF_VL(s) + lr * 72 + lch * 16,     &g_Vml[go]);                   \
        cp16(LF_VL(s) + lr * 72 + lch * 16 + 8, &g_Vml[go + 8]); }

    uint32_t qh[4][4], ql[4][4];
    const int qr0 = rowbase + qb * 128 + warp * 16 + g;
    const float* P0 = &g_Pf[(size_t)qr0 * LC + h * 64];
    const float* P1 = &g_Pf[(size_t)(qr0 + 8) * LC + h * 64];
#pragma unroll
    for (int ks = 0; ks < 4; ks++) {
        int c0 = ks * 16 + 2 * tig;
        pack_hl(P0[c0],     P0[c0 + 1], qh[ks][0], ql[ks][0]);
        pack_hl(P1[c0],     P1[c0 + 1], qh[ks][1], ql[ks][1]);
        pack_hl(P0[c0 + 8], P0[c0 + 9], qh[ks][2], ql[ks][2]);
        pack_hl(P1[c0 + 8], P1[c0 + 9], qh[ks][3], ql[ks][3]);
    }

    LF_ISS(0, 0); asm volatile("cp.async.commit_group;");

    float of[8][4];
#pragma unroll
    for (int nf = 0; nf < 8; nf++)
#pragma unroll
        for (int i = 0; i < 4; i++) of[nf][i] = 0.f;
    float m0 = -1e30f, m1 = -1e30f, l0 = 0.f, l1 = 0.f;

    for (int kt = 0; kt < 32; kt++) {
        const int s = kt & 1;
        if (kt + 1 < 32) { LF_ISS(kt + 1, s ^ 1); }
        asm volatile("cp.async.commit_group;");
        asm volatile("cp.async.wait_group 1;");
        __syncthreads();

        __nv_bfloat16* Kh = LF_KH(s);
        __nv_bfloat16* Kl = LF_KL(s);
        __nv_bfloat16* Vh = LF_VH(s);
        __nv_bfloat16* Vl = LF_VL(s);

        float sf[8][4];
#pragma unroll
        for (int nfp = 0; nfp < 4; nfp++) {
#pragma unroll
            for (int i = 0; i < 4; i++) { sf[2*nfp][i] = 0.f; sf[2*nfp+1][i] = 0.f; }
#pragma unroll
            for (int ks = 0; ks < 4; ks++) {
                uint32_t kh4[4], kl4[4];
                int row = nfp * 16 + (lane & 15);
                int col = ks * 16 + (lane >> 4) * 8;
                ldsm_x4(kh4, cvta_s(&Kh[row * 72 + col]));
                ldsm_x4(kl4, cvta_s(&Kl[row * 72 + col]));
                mma_bf16b(sf[2 * nfp],     qh[ks], kh4[0], kh4[2]);
                mma_bf16b(sf[2 * nfp],     ql[ks], kh4[0], kh4[2]);
                mma_bf16b(sf[2 * nfp],     qh[ks], kl4[0], kl4[2]);
                mma_bf16b(sf[2 * nfp + 1], qh[ks], kh4[1], kh4[3]);
                mma_bf16b(sf[2 * nfp + 1], ql[ks], kh4[1], kh4[3]);
                mma_bf16b(sf[2 * nfp + 1], qh[ks], kl4[1], kl4[3]);
            }
        }

        float mx0 = -1e30f, mx1 = -1e30f;
#pragma unroll
        for (int nf = 0; nf < 8; nf++) {
            sf[nf][0] *= 0.125f; sf[nf][1] *= 0.125f;
            sf[nf][2] *= 0.125f; sf[nf][3] *= 0.125f;
            mx0 = fmaxf(mx0, fmaxf(sf[nf][0], sf[nf][1]));
            mx1 = fmaxf(mx1, fmaxf(sf[nf][2], sf[nf][3]));
        }
        mx0 = fmaxf(mx0, __shfl_xor_sync(~0u, mx0, 1));
        mx0 = fmaxf(mx0, __shfl_xor_sync(~0u, mx0, 2));
        mx1 = fmaxf(mx1, __shfl_xor_sync(~0u, mx1, 1));
        mx1 = fmaxf(mx1, __shfl_xor_sync(~0u, mx1, 2));
        float mn0 = fmaxf(m0, mx0), mn1 = fmaxf(m1, mx1);
        float cr0 = __expf(m0 - mn0), cr1 = __expf(m1 - mn1);
        m0 = mn0; m1 = mn1;

        float ps0 = 0.f, ps1 = 0.f;
        uint32_t pah[4][4];
#pragma unroll
        for (int nf = 0; nf < 8; nf++) {
            float p0 = __expf(sf[nf][0] - mn0), p1 = __expf(sf[nf][1] - mn0);
            float p2 = __expf(sf[nf][2] - mn1), p3 = __expf(sf[nf][3] - mn1);
            ps0 += p0 + p1; ps1 += p2 + p3;
            int ks = nf >> 1;
            if (nf & 1) { pah[ks][2] = pack_bf16(p0, p1); pah[ks][3] = pack_bf16(p2, p3); }
            else        { pah[ks][0] = pack_bf16(p0, p1); pah[ks][1] = pack_bf16(p2, p3); }
        }
        ps0 += __shfl_xor_sync(~0u, ps0, 1); ps0 += __shfl_xor_sync(~0u, ps0, 2);
        ps1 += __shfl_xor_sync(~0u, ps1, 1); ps1 += __shfl_xor_sync(~0u, ps1, 2);
        l0 = l0 * cr0 + ps0; l1 = l1 * cr1 + ps1;
#pragma unroll
        for (int nf = 0; nf < 8; nf++) {
            of[nf][0] *= cr0; of[nf][1] *= cr0; of[nf][2] *= cr1; of[nf][3] *= cr1;
        }
#pragma unroll
        for (int nfp = 0; nfp < 4; nfp++)
#pragma unroll
            for (int ks = 0; ks < 4; ks++) {
                uint32_t vh4[4], vl4[4];
                int row = ks * 16 + (lane & 15);
                int col = nfp * 16 + (lane >> 4) * 8;
                ldsm_x4t(vh4, cvta_s(&Vh[row * 72 + col]));
                ldsm_x4t(vl4, cvta_s(&Vl[row * 72 + col]));
                mma_bf16b(of[2 * nfp],     pah[ks], vh4[0], vh4[1]);
                mma_bf16b(of[2 * nfp],     pah[ks], vl4[0], vl4[1]);
                mma_bf16b(of[2 * nfp + 1], pah[ks], vh4[2], vh4[3]);
                mma_bf16b(of[2 * nfp + 1], pah[ks], vl4[2], vl4[3]);
            }
        __syncthreads();
    }

    const float inv0 = 1.f / l0, inv1 = 1.f / l1;
    const int r0 = rowbase + qb * 128 + warp * 16 + g;
#pragma unroll
    for (int nf = 0; nf < 8; nf++) {
        int col = (8 + h) * 64 + nf * 8 + 2 * tig;
        out[(size_t)r0 * HID + col]           = of[nf][0] * inv0;
        out[(size_t)r0 * HID + col + 1]       = of[nf][1] * inv0;
        out[(size_t)(r0 + 8) * HID + col]     = of[nf][2] * inv1;
        out[(size_t)(r0 + 8) * HID + col + 1] = of[nf][3] * inv1;
    }
}

// ---------------------------------------------------------------------------
extern "C" void kernel_launch(void* const* d_in, const int* in_sizes, int n_in,
                              void* d_out, int out_size) {
    (void)in_sizes; (void)n_in; (void)out_size;
    const float* X    = (const float*)d_in[0];
    const float* mask = (const float*)d_in[1];
    ProjArgs pa;
    for (int i = 0; i < 8; i++) {
        pa.w[i] = (const float*)d_in[2 + 2 * i];
        pa.b[i] = (const float*)d_in[3 + 2 * i];
    }
    float* out = (float*)d_out;

    const int PGSMEM = 61440 + 512;
    const int PLSMEM = 122880 + 512;
    const int GFSMEM = 26624 + 3 * 18432;   // 81920
    const int LFSMEM = 2 * 36864;           // 73728
    cudaFuncSetAttribute(proj_g, cudaFuncAttributeMaxDynamicSharedMemorySize, PGSMEM);
    cudaFuncSetAttribute(proj_l, cudaFuncAttributeMaxDynamicSharedMemorySize, PLSMEM);
    cudaFuncSetAttribute(flash_global, cudaFuncAttributeMaxDynamicSharedMemorySize, GFSMEM);
    cudaFuncSetAttribute(flash_local, cudaFuncAttributeMaxDynamicSharedMemorySize, LFSMEM);

    split_X<<<4096, 256>>>(X);
    transW<<<dim3(16, 32, 8), 256>>>(pa);
    bias_cat<<<16, 256>>>(pa);
    proj_l<<<dim3(20, 32), 256, PLSMEM>>>();
    proj_g<<<dim3(12, 32), 256, PGSMEM>>>();
    compute_M_part<<<dim3(16, 8), 256>>>();
    reduce_M<<<256, 256>>>();
    lq_update<<<dim3(64, 8), 256>>>();
    prep_local<<<2048, 256>>>();
    flash_global<<<dim3(16, 16), 256, GFSMEM>>>(mask, out);
    flash_local<<<dim3(16, 16), 256, LFSMEM>>>(out);
}

// round 8
// speedup vs baseline: 1.1007x; 1.1007x over previous
#include <cuda_runtime.h>
#include <cuda_bf16.h>
#include <cstdint>

#define SEQ 2048
#define NROWS 4096
#define HID 1024
#define GC 1536   // global proj cols: Q 0, K 512, V 1024
#define LC 2560   // local proj cols: LQ 0, LK1 512, LK2 1024, LV1 1536, LV2 2048

__device__ __nv_bfloat16 g_Xh[(size_t)NROWS * HID];
__device__ __nv_bfloat16 g_Xl[(size_t)NROWS * HID];
__device__ __nv_bfloat16 g_Wth[(size_t)4096 * HID];   // all 8 W, transposed [n][k]
__device__ __nv_bfloat16 g_Wtl[(size_t)4096 * HID];
__device__ float g_bias[4096];
__device__ __nv_bfloat16 g_Pg[(size_t)NROWS * GC];    // global projections bf16
__device__ float g_Pf[(size_t)NROWS * LC];            // local projections fp32
__device__ float g_Mpart[8 * 16 * 64 * 64];
__device__ float g_M[16 * 64 * 64];
// precomputed flash_local operand planes (bf16 hi/lo)
__device__ __nv_bfloat16 g_K2h[(size_t)NROWS * 512];
__device__ __nv_bfloat16 g_K2l[(size_t)NROWS * 512];
__device__ __nv_bfloat16 g_Vmh[(size_t)NROWS * 512];
__device__ __nv_bfloat16 g_Vml[(size_t)NROWS * 512];

struct ProjArgs { const float* w[8]; const float* b[8]; };

// ---------------- helpers ----------------
__device__ __forceinline__ uint32_t cvta_s(const void* p) {
    return (uint32_t)__cvta_generic_to_shared(p);
}
__device__ __forceinline__ void cp16(void* smem, const void* gmem) {
    asm volatile("cp.async.cg.shared.global [%0], [%1], 16;"
                 :: "r"(cvta_s(smem)), "l"(gmem));
}
__device__ __forceinline__ void ldsm_x4(uint32_t r[4], uint32_t a) {
    asm volatile("ldmatrix.sync.aligned.m8n8.x4.shared.b16 {%0,%1,%2,%3}, [%4];"
                 : "=r"(r[0]), "=r"(r[1]), "=r"(r[2]), "=r"(r[3]) : "r"(a));
}
__device__ __forceinline__ void ldsm_x4t(uint32_t r[4], uint32_t a) {
    asm volatile("ldmatrix.sync.aligned.m8n8.x4.trans.shared.b16 {%0,%1,%2,%3}, [%4];"
                 : "=r"(r[0]), "=r"(r[1]), "=r"(r[2]), "=r"(r[3]) : "r"(a));
}
__device__ __forceinline__ void mma_bf16b(float c[4], const uint32_t a[4], uint32_t b0, uint32_t b1) {
    asm volatile("mma.sync.aligned.m16n8k16.row.col.f32.bf16.bf16.f32 "
                 "{%0,%1,%2,%3},{%4,%5,%6,%7},{%8,%9},{%0,%1,%2,%3};"
                 : "+f"(c[0]), "+f"(c[1]), "+f"(c[2]), "+f"(c[3])
                 : "r"(a[0]), "r"(a[1]), "r"(a[2]), "r"(a[3]), "r"(b0), "r"(b1));
}
__device__ __forceinline__ void split2(float x, __nv_bfloat16& h, __nv_bfloat16& l) {
    h = __float2bfloat16_rn(x);
    l = __float2bfloat16_rn(x - __bfloat162float(h));
}
__device__ __forceinline__ uint32_t pack_bf16(float a, float b) {
    __nv_bfloat162 t = __floats2bfloat162_rn(a, b);
    return *(uint32_t*)&t;
}
__device__ __forceinline__ void pack_hl(float a, float b, uint32_t& h, uint32_t& l) {
    __nv_bfloat162 hh = __floats2bfloat162_rn(a, b);
    __nv_bfloat162 ll = __floats2bfloat162_rn(a - __bfloat162float(hh.x),
                                              b - __bfloat162float(hh.y));
    h = *(uint32_t*)&hh; l = *(uint32_t*)&ll;
}

// ---------------- prep kernels ----------------
__global__ void split_X(const float* __restrict__ X) {
    int t = blockIdx.x * 256 + threadIdx.x;
    float4 v = *(const float4*)&X[(size_t)t * 4];
    __nv_bfloat16 h, l;
    split2(v.x, h, l); g_Xh[(size_t)t*4+0] = h; g_Xl[(size_t)t*4+0] = l;
    split2(v.y, h, l); g_Xh[(size_t)t*4+1] = h; g_Xl[(size_t)t*4+1] = l;
    split2(v.z, h, l); g_Xh[(size_t)t*4+2] = h; g_Xl[(size_t)t*4+2] = l;
    split2(v.w, h, l); g_Xh[(size_t)t*4+3] = h; g_Xl[(size_t)t*4+3] = l;
}

__global__ void transW(ProjArgs pa) {
    __shared__ float tile[32][33];
    const int nb = blockIdx.x, kb = blockIdx.y, w = blockIdx.z;
    const float* __restrict__ W = pa.w[w];
    const int tx = threadIdx.x & 31, ty0 = threadIdx.x >> 5;
#pragma unroll
    for (int i = 0; i < 4; i++) {
        int ty = ty0 + 8 * i;
        tile[ty][tx] = W[(size_t)(kb * 32 + ty) * 512 + nb * 32 + tx];
    }
    __syncthreads();
#pragma unroll
    for (int i = 0; i < 4; i++) {
        int ty = ty0 + 8 * i;
        __nv_bfloat16 h, l; split2(tile[tx][ty], h, l);
        size_t o = (size_t)(w * 512 + nb * 32 + ty) * HID + kb * 32 + tx;
        g_Wth[o] = h; g_Wtl[o] = l;
    }
}

__global__ void bias_cat(ProjArgs pa) {
    int t = blockIdx.x * 256 + threadIdx.x;
    g_bias[t] = pa.b[t >> 9][t & 511];
}

// prep for flash_local: bf16 hi/lo LK2 planes + bf16 hi/lo merged-V planes
__global__ void prep_local() {
    int t = blockIdx.x * 256 + threadIdx.x;      // 4096*128
    int r = t >> 7, c4 = (t & 127) * 4;
    size_t grow = (size_t)r * LC;
    size_t po = (size_t)r * 512 + c4;
    float4 k = *(const float4*)&g_Pf[grow + 1024 + c4];
    __nv_bfloat162 h01, h23, l01, l23;
    split2(k.x, h01.x, l01.x); split2(k.y, h01.y, l01.y);
    split2(k.z, h23.x, l23.x); split2(k.w, h23.y, l23.y);
    *(__nv_bfloat162*)&g_K2h[po]     = h01;
    *(__nv_bfloat162*)&g_K2h[po + 2] = h23;
    *(__nv_bfloat162*)&g_K2l[po]     = l01;
    *(__nv_bfloat162*)&g_K2l[po + 2] = l23;
    float4 v1 = *(const float4*)&g_Pf[grow + 1536 + c4];
    float4 v2 = *(const float4*)&g_Pf[grow + 2048 + c4];
    split2(v1.x + v2.x, h01.x, l01.x); split2(v1.y + v2.y, h01.y, l01.y);
    split2(v1.z + v2.z, h23.x, l23.x); split2(v1.w + v2.w, h23.y, l23.y);
    *(__nv_bfloat162*)&g_Vmh[po]     = h01;
    *(__nv_bfloat162*)&g_Vmh[po + 2] = h23;
    *(__nv_bfloat162*)&g_Vml[po]     = l01;
    *(__nv_bfloat162*)&g_Vml[po + 2] = l23;
}

// ---------------- merged projection GEMM ----------------
// grid.x = 1024: [0,640) local CTAs (3-term, 2-stage), [640,1024) global (1-term, 3-stage)
__global__ __launch_bounds__(256, 2) void proj_all() {
    extern __shared__ char psm[];
    __nv_bfloat16* SB = (__nv_bfloat16*)psm;
    float* sbias = (float*)(psm + 81920);
    const int bx = blockIdx.x;
    const int tid = threadIdx.x, lane = tid & 31, warp = tid >> 5;
    const int wr = warp >> 1, wc = warp & 1;
    const int g = lane >> 2, tig = lane & 3;
    const int lr = tid >> 2, lch = tid & 3;

    float c[2][8][4];
#pragma unroll
    for (int mf = 0; mf < 2; mf++)
#pragma unroll
        for (int nf = 0; nf < 8; nf++)
#pragma unroll
            for (int i = 0; i < 4; i++) c[mf][nf][i] = 0.f;

    if (bx < 640) {
        // ----- local path: 3-term hi/lo, 2-stage pipeline -----
        const int bn = bx % 20, bm = bx / 20;
        if (tid < 128) sbias[tid] = g_bias[GC + bn * 128 + tid];

#define LP_AH(s) (SB + (s) * 20480)
#define LP_BH(s) (SB + (s) * 20480 + 5120)
#define LP_AL(s) (SB + (s) * 20480 + 10240)
#define LP_BL(s) (SB + (s) * 20480 + 15360)
#define LP_ISS(kt, s) {                                                        \
        int k0 = (kt) * 32;                                                    \
        size_t ga0 = (size_t)(bm * 128 + lr) * HID + k0 + lch * 8;             \
        size_t gb0 = (size_t)(GC + bn * 128 + lr) * HID + k0 + lch * 8;        \
        cp16(LP_AH(s) + lr * 40 + lch * 8,        g_Xh + ga0);                 \
        cp16(LP_AH(s) + (lr + 64) * 40 + lch * 8, g_Xh + ga0 + 64 * HID);      \
        cp16(LP_BH(s) + lr * 40 + lch * 8,        g_Wth + gb0);                \
        cp16(LP_BH(s) + (lr + 64) * 40 + lch * 8, g_Wth + gb0 + 64 * HID);     \
        cp16(LP_AL(s) + lr * 40 + lch * 8,        g_Xl + ga0);                 \
        cp16(LP_AL(s) + (lr + 64) * 40 + lch * 8, g_Xl + ga0 + 64 * HID);      \
        cp16(LP_BL(s) + lr * 40 + lch * 8,        g_Wtl + gb0);                \
        cp16(LP_BL(s) + (lr + 64) * 40 + lch * 8, g_Wtl + gb0 + 64 * HID); }

        LP_ISS(0, 0); asm volatile("cp.async.commit_group;");

        for (int kt = 0; kt < 32; kt++) {
            const int s = kt & 1;
            if (kt + 1 < 32) { LP_ISS(kt + 1, s ^ 1); }
            asm volatile("cp.async.commit_group;");
            asm volatile("cp.async.wait_group 1;");
            __syncthreads();

            __nv_bfloat16* Ah = LP_AH(s);
            __nv_bfloat16* Bh = LP_BH(s);
            __nv_bfloat16* Al = LP_AL(s);
            __nv_bfloat16* Bl = LP_BL(s);
            uint32_t ah[2][2][4], al[2][2][4];
#pragma unroll
            for (int mf = 0; mf < 2; mf++)
#pragma unroll
                for (int ks = 0; ks < 2; ks++) {
                    int row = wr * 32 + mf * 16 + (lane & 15);
                    int col = ks * 16 + (lane >> 4) * 8;
                    ldsm_x4(ah[mf][ks], cvta_s(&Ah[row * 40 + col]));
                    ldsm_x4(al[mf][ks], cvta_s(&Al[row * 40 + col]));
                }
#pragma unroll
            for (int nfp = 0; nfp < 4; nfp++) {
#pragma unroll
                for (int ks = 0; ks < 2; ks++) {
                    uint32_t bh4[4], bl4[4];
                    int row = wc * 64 + nfp * 16 + (lane & 15);
                    int col = ks * 16 + (lane >> 4) * 8;
                    ldsm_x4(bh4, cvta_s(&Bh[row * 40 + col]));
                    ldsm_x4(bl4, cvta_s(&Bl[row * 40 + col]));
#pragma unroll
                    for (int mf = 0; mf < 2; mf++) {
                        mma_bf16b(c[mf][2 * nfp],     ah[mf][ks], bh4[0], bh4[2]);
                        mma_bf16b(c[mf][2 * nfp],     al[mf][ks], bh4[0], bh4[2]);
                        mma_bf16b(c[mf][2 * nfp],     ah[mf][ks], bl4[0], bl4[2]);
                        mma_bf16b(c[mf][2 * nfp + 1], ah[mf][ks], bh4[1], bh4[3]);
                        mma_bf16b(c[mf][2 * nfp + 1], al[mf][ks], bh4[1], bh4[3]);
                        mma_bf16b(c[mf][2 * nfp + 1], ah[mf][ks], bl4[1], bl4[3]);
                    }
                }
            }
            __syncthreads();
        }

#pragma unroll
        for (int mf = 0; mf < 2; mf++)
#pragma unroll
            for (int nf = 0; nf < 8; nf++) {
                int lcol = wc * 64 + nf * 8 + 2 * tig;
                int fc = bn * 128 + lcol;
                int r0 = bm * 128 + wr * 32 + mf * 16 + g;
                g_Pf[(size_t)r0 * LC + fc]           = c[mf][nf][0] + sbias[lcol];
                g_Pf[(size_t)r0 * LC + fc + 1]       = c[mf][nf][1] + sbias[lcol + 1];
                g_Pf[(size_t)(r0 + 8) * LC + fc]     = c[mf][nf][2] + sbias[lcol];
                g_Pf[(size_t)(r0 + 8) * LC + fc + 1] = c[mf][nf][3] + sbias[lcol + 1];
            }
    } else {
        // ----- global path: 1-term, 3-stage pipeline -----
        const int y = bx - 640;
        const int bn = y % 12, bm = y / 12;
        if (tid < 128) sbias[tid] = g_bias[bn * 128 + tid];

#define GP_A(s) (SB + (s) * 5120)
#define GP_B(s) (SB + 15360 + (s) * 5120)
#define GP_ISS(kt, s) {                                                        \
        int k0 = (kt) * 32;                                                    \
        size_t ga0 = (size_t)(bm * 128 + lr) * HID + k0 + lch * 8;             \
        size_t gb0 = (size_t)(bn * 128 + lr) * HID + k0 + lch * 8;             \
        cp16(GP_A(s) + lr * 40 + lch * 8,        g_Xh + ga0);                  \
        cp16(GP_A(s) + (lr + 64) * 40 + lch * 8, g_Xh + ga0 + 64 * HID);       \
        cp16(GP_B(s) + lr * 40 + lch * 8,        g_Wth + gb0);                 \
        cp16(GP_B(s) + (lr + 64) * 40 + lch * 8, g_Wth + gb0 + 64 * HID); }

        GP_ISS(0, 0); asm volatile("cp.async.commit_group;");
        GP_ISS(1, 1); asm volatile("cp.async.commit_group;");

        for (int kt = 0; kt < 32; kt++) {
            const int s = kt % 3;
            asm volatile("cp.async.wait_group 1;");
            __syncthreads();
            if (kt + 2 < 32) { GP_ISS(kt + 2, (kt + 2) % 3); }
            asm volatile("cp.async.commit_group;");

            __nv_bfloat16* Ah = GP_A(s);
            __nv_bfloat16* Bh = GP_B(s);
            uint32_t ah[2][2][4];
#pragma unroll
            for (int mf = 0; mf < 2; mf++)
#pragma unroll
                for (int ks = 0; ks < 2; ks++) {
                    int row = wr * 32 + mf * 16 + (lane & 15);
                    int col = ks * 16 + (lane >> 4) * 8;
                    ldsm_x4(ah[mf][ks], cvta_s(&Ah[row * 40 + col]));
                }
#pragma unroll
            for (int nfp = 0; nfp < 4; nfp++) {
#pragma unroll
                for (int ks = 0; ks < 2; ks++) {
                    uint32_t b4[4];
                    int row = wc * 64 + nfp * 16 + (lane & 15);
                    int col = ks * 16 + (lane >> 4) * 8;
                    ldsm_x4(b4, cvta_s(&Bh[row * 40 + col]));
#pragma unroll
                    for (int mf = 0; mf < 2; mf++) {
                        mma_bf16b(c[mf][2 * nfp],     ah[mf][ks], b4[0], b4[2]);
                        mma_bf16b(c[mf][2 * nfp + 1], ah[mf][ks], b4[1], b4[3]);
                    }
                }
            }
        }

#pragma unroll
        for (int mf = 0; mf < 2; mf++)
#pragma unroll
            for (int nf = 0; nf < 8; nf++) {
                int lcol = wc * 64 + nf * 8 + 2 * tig;
                int gcol = bn * 128 + lcol;
                int r0 = bm * 128 + wr * 32 + mf * 16 + g;
                float v0 = c[mf][nf][0] + sbias[lcol];
                float v1 = c[mf][nf][1] + sbias[lcol + 1];
                float v2 = c[mf][nf][2] + sbias[lcol];
                float v3 = c[mf][nf][3] + sbias[lcol + 1];
                *(uint32_t*)&g_Pg[(size_t)r0 * GC + gcol]       = pack_bf16(v0, v1);
                *(uint32_t*)&g_Pg[(size_t)(r0 + 8) * GC + gcol] = pack_bf16(v2, v3);
            }
    }
}

// ---------------- M = lk1^T lk1 (fp32) ----------------
__global__ __launch_bounds__(256) void compute_M_part() {
    __shared__ float Ls[64 * 68];
    const int bh = blockIdx.x, b = bh >> 3, h = bh & 7;
    const int part = blockIdx.y;
    const int tid = threadIdx.x, e = tid & 63, d0 = tid >> 6;
    float acc[16];
#pragma unroll
    for (int i = 0; i < 16; i++) acc[i] = 0.f;
    const int colbase = 512 + h * 64;
    for (int t = 0; t < 4; t++) {
        const int s0 = (part * 4 + t) * 64;
        __syncthreads();
#pragma unroll
        for (int ch = 0; ch < 4; ch++) {
            int idx = tid + 256 * ch;
            int r = idx >> 4, c4 = (idx & 15) * 4;
            *(float4*)&Ls[r * 68 + c4] =
                *(const float4*)&g_Pf[(size_t)(b * SEQ + s0 + r) * LC + colbase + c4];
        }
        __syncthreads();
        for (int r = 0; r < 64; r++) {
            float le = Ls[r * 68 + e];
#pragma unroll
            for (int i = 0; i < 16; i++)
                acc[i] += Ls[r * 68 + d0 + 4 * i] * le;
        }
    }
#pragma unroll
    for (int i = 0; i < 16; i++)
        g_Mpart[((size_t)part * 16 + bh) * 4096 + (d0 + 4 * i) * 64 + e] = acc[i];
}

__global__ __launch_bounds__(256) void reduce_M() {
    const int t = blockIdx.x * 256 + threadIdx.x;
    const int bh = t >> 12, idx = t & 4095;
    float s = 0.f;
#pragma unroll
    for (int p = 0; p < 8; p++) s += g_Mpart[((size_t)p * 16 + bh) * 4096 + idx];
    g_M[(size_t)bh * 4096 + idx] = s;
}

// ---------------- LQ' = LQ @ M (fp32, in place) ----------------
__global__ __launch_bounds__(256) void lq_update() {
    __shared__ float Ms[64 * 65];
    __shared__ float Ls[64 * 68];
    const int rb = blockIdx.x, h = blockIdx.y;
    const int row0 = rb * 64, b = row0 >> 11, bh = b * 8 + h;
    const int tid = threadIdx.x;
    const int colbase = h * 64;
#pragma unroll
    for (int ch = 0; ch < 16; ch++) {
        int idx = tid + 256 * ch;
        Ms[(idx >> 6) * 65 + (idx & 63)] = g_M[(size_t)bh * 4096 + idx];
    }
#pragma unroll
    for (int ch = 0; ch < 4; ch++) {
        int idx = tid + 256 * ch;
        int r = idx >> 4, c4 = (idx & 15) * 4;
        *(float4*)&Ls[r * 68 + c4] =
            *(const float4*)&g_Pf[(size_t)(row0 + r) * LC + colbase + c4];
    }
    __syncthreads();
    const int e = tid & 63, r0 = tid >> 6;
    float acc[16];
#pragma unroll
    for (int i = 0; i < 16; i++) acc[i] = 0.f;
    for (int d = 0; d < 64; d++) {
        float mv = Ms[d * 65 + e];
#pragma unroll
        for (int i = 0; i < 16; i++)
            acc[i] += Ls[(r0 + 4 * i) * 68 + d] * mv;
    }
#pragma unroll
    for (int i = 0; i < 16; i++)
        g_Pf[(size_t)(row0 + r0 + 4 * i) * LC + colbase + e] = acc[i];
}

// ---------------- global flash: BM=128, 3-stage pipeline, 2 CTAs/SM ----------------
__global__ __launch_bounds__(256, 2) void flash_global(const float* __restrict__ mask,
                                                       float* __restrict__ out) {
    extern __shared__ char gsm[];
    __nv_bfloat16* Qs = (__nv_bfloat16*)gsm;                 // 128*72
    float* maskS = (float*)(gsm + 18432);                    // 2048 floats
#define GF_K(s) ((__nv_bfloat16*)(gsm + 26624 + (s) * 18432))
#define GF_V(s) ((__nv_bfloat16*)(gsm + 26624 + (s) * 18432 + 9216))
    const int tid = threadIdx.x, lane = tid & 31, warp = tid >> 5;
    const int g = lane >> 2, tig = lane & 3;
    const int qb = blockIdx.x, by = blockIdx.y;
    const int b = by >> 3, h = by & 7;
    const int qcol = h * 64, kcol = 512 + h * 64, vcol = 1024 + h * 64;
    const int rowbase = b * SEQ;
    const int lr = tid >> 2, lch = tid & 3;

#define GF_ISS(kt, s) {                                                        \
        size_t grow = (size_t)(rowbase + (kt) * 64 + lr) * GC;                 \
        cp16(GF_K(s) + lr * 72 + lch * 16,     &g_Pg[grow + kcol + lch * 16]); \
        cp16(GF_K(s) + lr * 72 + lch * 16 + 8, &g_Pg[grow + kcol + lch * 16 + 8]); \
        cp16(GF_V(s) + lr * 72 + lch * 16,     &g_Pg[grow + vcol + lch * 16]); \
        cp16(GF_V(s) + lr * 72 + lch * 16 + 8, &g_Pg[grow + vcol + lch * 16 + 8]); }

#pragma unroll
    for (int i = 0; i < 8; i++) maskS[tid + 256 * i] = mask[b * SEQ + tid + 256 * i];
#pragma unroll
    for (int i = 0; i < 4; i++) {
        int idx = tid + 256 * i;
        int r = idx >> 3, ch = idx & 7;
        *(uint4*)&Qs[r * 72 + ch * 8] =
            *(const uint4*)&g_Pg[(size_t)(rowbase + qb * 128 + r) * GC + qcol + ch * 8];
    }
    GF_ISS(0, 0); asm volatile("cp.async.commit_group;");
    GF_ISS(1, 1); asm volatile("cp.async.commit_group;");
    __syncthreads();

    uint32_t qf[4][4];
#pragma unroll
    for (int ks = 0; ks < 4; ks++) {
        int row = warp * 16 + (lane & 15);
        int col = ks * 16 + (lane >> 4) * 8;
        ldsm_x4(qf[ks], cvta_s(&Qs[row * 72 + col]));
    }

    float of[8][4];
#pragma unroll
    for (int nf = 0; nf < 8; nf++)
#pragma unroll
        for (int i = 0; i < 4; i++) of[nf][i] = 0.f;
    float m0 = -1e30f, m1 = -1e30f, l0 = 0.f, l1 = 0.f;

    for (int kt = 0; kt < 32; kt++) {
        const int s = kt % 3;
        asm volatile("cp.async.wait_group 1;");
        __syncthreads();
        if (kt + 2 < 32) { GF_ISS(kt + 2, (kt + 2) % 3); }
        asm volatile("cp.async.commit_group;");

        __nv_bfloat16* Ks = GF_K(s);
        __nv_bfloat16* Vs = GF_V(s);

        float sf[8][4];
#pragma unroll
        for (int nfp = 0; nfp < 4; nfp++) {
#pragma unroll
            for (int i = 0; i < 4; i++) { sf[2*nfp][i] = 0.f; sf[2*nfp+1][i] = 0.f; }
#pragma unroll
            for (int ks = 0; ks < 4; ks++) {
                uint32_t k4[4];
                int row = nfp * 16 + (lane & 15);
                int col = ks * 16 + (lane >> 4) * 8;
                ldsm_x4(k4, cvta_s(&Ks[row * 72 + col]));
                mma_bf16b(sf[2 * nfp],     qf[ks], k4[0], k4[2]);
                mma_bf16b(sf[2 * nfp + 1], qf[ks], k4[1], k4[3]);
            }
        }

        float mx0 = -1e30f, mx1 = -1e30f;
#pragma unroll
        for (int nf = 0; nf < 8; nf++) {
            float a0 = maskS[kt * 64 + nf * 8 + 2 * tig];
            float a1 = maskS[kt * 64 + nf * 8 + 2 * tig + 1];
            sf[nf][0] = sf[nf][0] * 0.125f + a0;
            sf[nf][1] = sf[nf][1] * 0.125f + a1;
            sf[nf][2] = sf[nf][2] * 0.125f + a0;
            sf[nf][3] = sf[nf][3] * 0.125f + a1;
            mx0 = fmaxf(mx0, fmaxf(sf[nf][0], sf[nf][1]));
            mx1 = fmaxf(mx1, fmaxf(sf[nf][2], sf[nf][3]));
        }
        mx0 = fmaxf(mx0, __shfl_xor_sync(~0u, mx0, 1));
        mx0 = fmaxf(mx0, __shfl_xor_sync(~0u, mx0, 2));
        mx1 = fmaxf(mx1, __shfl_xor_sync(~0u, mx1, 1));
        mx1 = fmaxf(mx1, __shfl_xor_sync(~0u, mx1, 2));
        float mn0 = fmaxf(m0, mx0), mn1 = fmaxf(m1, mx1);
        float cr0 = __expf(m0 - mn0), cr1 = __expf(m1 - mn1);
        m0 = mn0; m1 = mn1;

        float ps0 = 0.f, ps1 = 0.f;
        uint32_t pa[4][4];
#pragma unroll
        for (int nf = 0; nf < 8; nf++) {
            float p0 = __expf(sf[nf][0] - mn0), p1 = __expf(sf[nf][1] - mn0);
            float p2 = __expf(sf[nf][2] - mn1), p3 = __expf(sf[nf][3] - mn1);
            ps0 += p0 + p1; ps1 += p2 + p3;
            int ks = nf >> 1;
            if (nf & 1) { pa[ks][2] = pack_bf16(p0, p1); pa[ks][3] = pack_bf16(p2, p3); }
            else        { pa[ks][0] = pack_bf16(p0, p1); pa[ks][1] = pack_bf16(p2, p3); }
        }
        ps0 += __shfl_xor_sync(~0u, ps0, 1); ps0 += __shfl_xor_sync(~0u, ps0, 2);
        ps1 += __shfl_xor_sync(~0u, ps1, 1); ps1 += __shfl_xor_sync(~0u, ps1, 2);
        l0 = l0 * cr0 + ps0; l1 = l1 * cr1 + ps1;
#pragma unroll
        for (int nf = 0; nf < 8; nf++) {
            of[nf][0] *= cr0; of[nf][1] *= cr0; of[nf][2] *= cr1; of[nf][3] *= cr1;
        }
#pragma unroll
        for (int nfp = 0; nfp < 4; nfp++)
#pragma unroll
            for (int ks = 0; ks < 4; ks++) {
                uint32_t v4[4];
                int row = ks * 16 + (lane & 15);
                int col = nfp * 16 + (lane >> 4) * 8;
                ldsm_x4t(v4, cvta_s(&Vs[row * 72 + col]));
                mma_bf16b(of[2 * nfp],     pa[ks], v4[0], v4[1]);
                mma_bf16b(of[2 * nfp + 1], pa[ks], v4[2], v4[3]);
            }
    }

    const float inv0 = 1.f / l0, inv1 = 1.f / l1;
    const int r0 = rowbase + qb * 128 + warp * 16 + g;
#pragma unroll
    for (int nf = 0; nf < 8; nf++) {
        int col = h * 64 + nf * 8 + 2 * tig;
        out[(size_t)r0 * HID + col]           = of[nf][0] * inv0;
        out[(size_t)r0 * HID + col + 1]       = of[nf][1] * inv0;
        out[(size_t)(r0 + 8) * HID + col]     = of[nf][2] * inv1;
        out[(size_t)(r0 + 8) * HID + col + 1] = of[nf][3] * inv1;
    }
}

// ---------------- local flash: bf16 3-term QK, 2-term PV, 2 CTAs/SM ----------------
__global__ __launch_bounds__(256, 2) void flash_local(float* __restrict__ out) {
    extern __shared__ char lsm[];
#define LF_KH(s) ((__nv_bfloat16*)(lsm + (s) * 36864))
#define LF_KL(s) ((__nv_bfloat16*)(lsm + (s) * 36864 + 9216))
#define LF_VH(s) ((__nv_bfloat16*)(lsm + (s) * 36864 + 18432))
#define LF_VL(s) ((__nv_bfloat16*)(lsm + (s) * 36864 + 27648))
    const int tid = threadIdx.x, lane = tid & 31, warp = tid >> 5;
    const int g = lane >> 2, tig = lane & 3;
    const int qb = blockIdx.x, by = blockIdx.y;
    const int b = by >> 3, h = by & 7;
    const int rowbase = b * SEQ;
    const int lr = tid >> 2, lch = tid & 3;

#define LF_ISS(kt, s) {                                                        \
        size_t go = (size_t)(rowbase + (kt) * 64 + lr) * 512 + h * 64 + lch * 16; \
        cp16(LF_KH(s) + lr * 72 + lch * 16,     &g_K2h[go]);                   \
        cp16(LF_KH(s) + lr * 72 + lch * 16 + 8, &g_K2h[go + 8]);               \
        cp16(LF_KL(s) + lr * 72 + lch * 16,     &g_K2l[go]);                   \
        cp16(LF_KL(s) + lr * 72 + lch * 16 + 8, &g_K2l[go + 8]);               \
        cp16(LF_VH(s) + lr * 72 + lch * 16,     &g_Vmh[go]);                   \
        cp16(LF_VH(s) + lr * 72 + lch * 16 + 8, &g_Vmh[go + 8]);               \
        cp16(LF_VL(s) + lr * 72 + lch * 16,     &g_Vml[go]);                   \
        cp16(LF_VL(s) + lr * 72 + lch * 16 + 8, &g_Vml[go + 8]); }

    uint32_t qh[4][4], ql[4][4];
    const int qr0 = rowbase + qb * 128 + warp * 16 + g;
    const float* P0 = &g_Pf[(size_t)qr0 * LC + h * 64];
    const float* P1 = &g_Pf[(size_t)(qr0 + 8) * LC + h * 64];
#pragma unroll
    for (int ks = 0; ks < 4; ks++) {
        int c0 = ks * 16 + 2 * tig;
        pack_hl(P0[c0],     P0[c0 + 1], qh[ks][0], ql[ks][0]);
        pack_hl(P1[c0],     P1[c0 + 1], qh[ks][1], ql[ks][1]);
        pack_hl(P0[c0 + 8], P0[c0 + 9], qh[ks][2], ql[ks][2]);
        pack_hl(P1[c0 + 8], P1[c0 + 9], qh[ks][3], ql[ks][3]);
    }

    LF_ISS(0, 0); asm volatile("cp.async.commit_group;");

    float of[8][4];
#pragma unroll
    for (int nf = 0; nf < 8; nf++)
#pragma unroll
        for (int i = 0; i < 4; i++) of[nf][i] = 0.f;
    float m0 = -1e30f, m1 = -1e30f, l0 = 0.f, l1 = 0.f;

    for (int kt = 0; kt < 32; kt++) {
        const int s = kt & 1;
        if (kt + 1 < 32) { LF_ISS(kt + 1, s ^ 1); }
        asm volatile("cp.async.commit_group;");
        asm volatile("cp.async.wait_group 1;");
        __syncthreads();

        __nv_bfloat16* Kh = LF_KH(s);
        __nv_bfloat16* Kl = LF_KL(s);
        __nv_bfloat16* Vh = LF_VH(s);
        __nv_bfloat16* Vl = LF_VL(s);

        float sf[8][4];
#pragma unroll
        for (int nfp = 0; nfp < 4; nfp++) {
#pragma unroll
            for (int i = 0; i < 4; i++) { sf[2*nfp][i] = 0.f; sf[2*nfp+1][i] = 0.f; }
#pragma unroll
            for (int ks = 0; ks < 4; ks++) {
                uint32_t kh4[4], kl4[4];
                int row = nfp * 16 + (lane & 15);
                int col = ks * 16 + (lane >> 4) * 8;
                ldsm_x4(kh4, cvta_s(&Kh[row * 72 + col]));
                ldsm_x4(kl4, cvta_s(&Kl[row * 72 + col]));
                mma_bf16b(sf[2 * nfp],     qh[ks], kh4[0], kh4[2]);
                mma_bf16b(sf[2 * nfp],     ql[ks], kh4[0], kh4[2]);
                mma_bf16b(sf[2 * nfp],     qh[ks], kl4[0], kl4[2]);
                mma_bf16b(sf[2 * nfp + 1], qh[ks], kh4[1], kh4[3]);
                mma_bf16b(sf[2 * nfp + 1], ql[ks], kh4[1], kh4[3]);
                mma_bf16b(sf[2 * nfp + 1], qh[ks], kl4[1], kl4[3]);
            }
        }

        float mx0 = -1e30f, mx1 = -1e30f;
#pragma unroll
        for (int nf = 0; nf < 8; nf++) {
            sf[nf][0] *= 0.125f; sf[nf][1] *= 0.125f;
            sf[nf][2] *= 0.125f; sf[nf][3] *= 0.125f;
            mx0 = fmaxf(mx0, fmaxf(sf[nf][0], sf[nf][1]));
            mx1 = fmaxf(mx1, fmaxf(sf[nf][2], sf[nf][3]));
        }
        mx0 = fmaxf(mx0, __shfl_xor_sync(~0u, mx0, 1));
        mx0 = fmaxf(mx0, __shfl_xor_sync(~0u, mx0, 2));
        mx1 = fmaxf(mx1, __shfl_xor_sync(~0u, mx1, 1));
        mx1 = fmaxf(mx1, __shfl_xor_sync(~0u, mx1, 2));
        float mn0 = fmaxf(m0, mx0), mn1 = fmaxf(m1, mx1);
        float cr0 = __expf(m0 - mn0), cr1 = __expf(m1 - mn1);
        m0 = mn0; m1 = mn1;

        float ps0 = 0.f, ps1 = 0.f;
        uint32_t pah[4][4];
#pragma unroll
        for (int nf = 0; nf < 8; nf++) {
            float p0 = __expf(sf[nf][0] - mn0), p1 = __expf(sf[nf][1] - mn0);
            float p2 = __expf(sf[nf][2] - mn1), p3 = __expf(sf[nf][3] - mn1);
            ps0 += p0 + p1; ps1 += p2 + p3;
            int ks = nf >> 1;
            if (nf & 1) { pah[ks][2] = pack_bf16(p0, p1); pah[ks][3] = pack_bf16(p2, p3); }
            else        { pah[ks][0] = pack_bf16(p0, p1); pah[ks][1] = pack_bf16(p2, p3); }
        }
        ps0 += __shfl_xor_sync(~0u, ps0, 1); ps0 += __shfl_xor_sync(~0u, ps0, 2);
        ps1 += __shfl_xor_sync(~0u, ps1, 1); ps1 += __shfl_xor_sync(~0u, ps1, 2);
        l0 = l0 * cr0 + ps0; l1 = l1 * cr1 + ps1;
#pragma unroll
        for (int nf = 0; nf < 8; nf++) {
            of[nf][0] *= cr0; of[nf][1] *= cr0; of[nf][2] *= cr1; of[nf][3] *= cr1;
        }
#pragma unroll
        for (int nfp = 0; nfp < 4; nfp++)
#pragma unroll
            for (int ks = 0; ks < 4; ks++) {
                uint32_t vh4[4], vl4[4];
                int row = ks * 16 + (lane & 15);
                int col = nfp * 16 + (lane >> 4) * 8;
                ldsm_x4t(vh4, cvta_s(&Vh[row * 72 + col]));
                ldsm_x4t(vl4, cvta_s(&Vl[row * 72 + col]));
                mma_bf16b(of[2 * nfp],     pah[ks], vh4[0], vh4[1]);
                mma_bf16b(of[2 * nfp],     pah[ks], vl4[0], vl4[1]);
                mma_bf16b(of[2 * nfp + 1], pah[ks], vh4[2], vh4[3]);
                mma_bf16b(of[2 * nfp + 1], pah[ks], vl4[2], vl4[3]);
            }
        __syncthreads();
    }

    const float inv0 = 1.f / l0, inv1 = 1.f / l1;
    const int r0 = rowbase + qb * 128 + warp * 16 + g;
#pragma unroll
    for (int nf = 0; nf < 8; nf++) {
        int col = (8 + h) * 64 + nf * 8 + 2 * tig;
        out[(size_t)r0 * HID + col]           = of[nf][0] * inv0;
        out[(size_t)r0 * HID + col + 1]       = of[nf][1] * inv0;
        out[(size_t)(r0 + 8) * HID + col]     = of[nf][2] * inv1;
        out[(size_t)(r0 + 8) * HID + col + 1] = of[nf][3] * inv1;
    }
}

// ---------------------------------------------------------------------------
extern "C" void kernel_launch(void* const* d_in, const int* in_sizes, int n_in,
                              void* d_out, int out_size) {
    (void)in_sizes; (void)n_in; (void)out_size;
    const float* X    = (const float*)d_in[0];
    const float* mask = (const float*)d_in[1];
    ProjArgs pa;
    for (int i = 0; i < 8; i++) {
        pa.w[i] = (const float*)d_in[2 + 2 * i];
        pa.b[i] = (const float*)d_in[3 + 2 * i];
    }
    float* out = (float*)d_out;

    const int PASMEM = 81920 + 512;         // proj_all (union of both paths)
    const int GFSMEM = 26624 + 3 * 18432;   // 81920
    const int LFSMEM = 2 * 36864;           // 73728
    cudaFuncSetAttribute(proj_all, cudaFuncAttributeMaxDynamicSharedMemorySize, PASMEM);
    cudaFuncSetAttribute(flash_global, cudaFuncAttributeMaxDynamicSharedMemorySize, GFSMEM);
    cudaFuncSetAttribute(flash_local, cudaFuncAttributeMaxDynamicSharedMemorySize, LFSMEM);

    split_X<<<4096, 256>>>(X);
    transW<<<dim3(16, 32, 8), 256>>>(pa);
    bias_cat<<<16, 256>>>(pa);
    proj_all<<<1024, 256, PASMEM>>>();
    compute_M_part<<<dim3(16, 8), 256>>>();
    reduce_M<<<256, 256>>>();
    lq_update<<<dim3(64, 8), 256>>>();
    prep_local<<<2048, 256>>>();
    flash_global<<<dim3(16, 16), 256, GFSMEM>>>(mask, out);
    flash_local<<<dim3(16, 16), 256, LFSMEM>>>(out);
}

// round 9
// speedup vs baseline: 1.1085x; 1.0071x over previous
#include <cuda_runtime.h>
#include <cuda_bf16.h>
#include <cstdint>

#define SEQ 2048
#define NROWS 4096
#define HID 1024
#define GC 1536   // global proj cols: Q 0, K 512, V 1024
#define LC 2560   // local proj cols: LQ 0, LK1 512, LK2 1024, LV1 1536, LV2 2048

__device__ __nv_bfloat16 g_Xh[(size_t)NROWS * HID];
__device__ __nv_bfloat16 g_Xl[(size_t)NROWS * HID];
__device__ __nv_bfloat16 g_Wth[(size_t)4096 * HID];   // all 8 W, transposed [n][k]
__device__ __nv_bfloat16 g_Wtl[(size_t)4096 * HID];
__device__ float g_bias[4096];
__device__ __nv_bfloat16 g_Pg[(size_t)NROWS * GC];    // global projections bf16
__device__ float g_Pf[(size_t)NROWS * LC];            // local projections fp32
__device__ float g_Mpart[8 * 16 * 64 * 64];
__device__ float g_M[16 * 64 * 64];
// precomputed flash_local operand planes (bf16 hi/lo)
__device__ __nv_bfloat16 g_K2h[(size_t)NROWS * 512];
__device__ __nv_bfloat16 g_K2l[(size_t)NROWS * 512];
__device__ __nv_bfloat16 g_Vmh[(size_t)NROWS * 512];
__device__ __nv_bfloat16 g_Vml[(size_t)NROWS * 512];

struct ProjArgs { const float* w[8]; const float* b[8]; };

// ---------------- helpers ----------------
__device__ __forceinline__ uint32_t cvta_s(const void* p) {
    return (uint32_t)__cvta_generic_to_shared(p);
}
__device__ __forceinline__ void cp16(void* smem, const void* gmem) {
    asm volatile("cp.async.cg.shared.global [%0], [%1], 16;"
                 :: "r"(cvta_s(smem)), "l"(gmem));
}
__device__ __forceinline__ void ldsm_x4(uint32_t r[4], uint32_t a) {
    asm volatile("ldmatrix.sync.aligned.m8n8.x4.shared.b16 {%0,%1,%2,%3}, [%4];"
                 : "=r"(r[0]), "=r"(r[1]), "=r"(r[2]), "=r"(r[3]) : "r"(a));
}
__device__ __forceinline__ void ldsm_x4t(uint32_t r[4], uint32_t a) {
    asm volatile("ldmatrix.sync.aligned.m8n8.x4.trans.shared.b16 {%0,%1,%2,%3}, [%4];"
                 : "=r"(r[0]), "=r"(r[1]), "=r"(r[2]), "=r"(r[3]) : "r"(a));
}
__device__ __forceinline__ void mma_bf16b(float c[4], const uint32_t a[4], uint32_t b0, uint32_t b1) {
    asm volatile("mma.sync.aligned.m16n8k16.row.col.f32.bf16.bf16.f32 "
                 "{%0,%1,%2,%3},{%4,%5,%6,%7},{%8,%9},{%0,%1,%2,%3};"
                 : "+f"(c[0]), "+f"(c[1]), "+f"(c[2]), "+f"(c[3])
                 : "r"(a[0]), "r"(a[1]), "r"(a[2]), "r"(a[3]), "r"(b0), "r"(b1));
}
__device__ __forceinline__ void split2(float x, __nv_bfloat16& h, __nv_bfloat16& l) {
    h = __float2bfloat16_rn(x);
    l = __float2bfloat16_rn(x - __bfloat162float(h));
}
__device__ __forceinline__ uint32_t pack_bf16(float a, float b) {
    __nv_bfloat162 t = __floats2bfloat162_rn(a, b);
    return *(uint32_t*)&t;
}
__device__ __forceinline__ void pack_hl(float a, float b, uint32_t& h, uint32_t& l) {
    __nv_bfloat162 hh = __floats2bfloat162_rn(a, b);
    __nv_bfloat162 ll = __floats2bfloat162_rn(a - __bfloat162float(hh.x),
                                              b - __bfloat162float(hh.y));
    h = *(uint32_t*)&hh; l = *(uint32_t*)&ll;
}

// ---------------- merged prep: split_X | transW | bias_cat ----------------
// grid = [0,4096) split_X, [4096,8192) transW, [8192,8208) bias
__global__ void prep_all(const float* __restrict__ X, ProjArgs pa) {
    __shared__ float tile[32][33];
    const int bx = blockIdx.x;
    const int tid = threadIdx.x;
    if (bx < 4096) {
        int t = bx * 256 + tid;
        float4 v = *(const float4*)&X[(size_t)t * 4];
        __nv_bfloat16 h, l;
        split2(v.x, h, l); g_Xh[(size_t)t*4+0] = h; g_Xl[(size_t)t*4+0] = l;
        split2(v.y, h, l); g_Xh[(size_t)t*4+1] = h; g_Xl[(size_t)t*4+1] = l;
        split2(v.z, h, l); g_Xh[(size_t)t*4+2] = h; g_Xl[(size_t)t*4+2] = l;
        split2(v.w, h, l); g_Xh[(size_t)t*4+3] = h; g_Xl[(size_t)t*4+3] = l;
    } else if (bx < 8192) {
        const int y = bx - 4096;
        const int nb = y & 15, kb = (y >> 4) & 31, w = y >> 9;
        const float* __restrict__ W = pa.w[w];
        const int tx = tid & 31, ty0 = tid >> 5;
#pragma unroll
        for (int i = 0; i < 4; i++) {
            int ty = ty0 + 8 * i;
            tile[ty][tx] = W[(size_t)(kb * 32 + ty) * 512 + nb * 32 + tx];
        }
        __syncthreads();
#pragma unroll
        for (int i = 0; i < 4; i++) {
            int ty = ty0 + 8 * i;
            __nv_bfloat16 h, l; split2(tile[tx][ty], h, l);
            size_t o = (size_t)(w * 512 + nb * 32 + ty) * HID + kb * 32 + tx;
            g_Wth[o] = h; g_Wtl[o] = l;
        }
    } else {
        int t = (bx - 8192) * 256 + tid;
        g_bias[t] = pa.b[t >> 9][t & 511];
    }
}

// prep for flash local: bf16 hi/lo LK2 planes + bf16 hi/lo merged-V planes
__global__ void prep_local() {
    int t = blockIdx.x * 256 + threadIdx.x;      // 4096*128
    int r = t >> 7, c4 = (t & 127) * 4;
    size_t grow = (size_t)r * LC;
    size_t po = (size_t)r * 512 + c4;
    float4 k = *(const float4*)&g_Pf[grow + 1024 + c4];
    __nv_bfloat162 h01, h23, l01, l23;
    split2(k.x, h01.x, l01.x); split2(k.y, h01.y, l01.y);
    split2(k.z, h23.x, l23.x); split2(k.w, h23.y, l23.y);
    *(__nv_bfloat162*)&g_K2h[po]     = h01;
    *(__nv_bfloat162*)&g_K2h[po + 2] = h23;
    *(__nv_bfloat162*)&g_K2l[po]     = l01;
    *(__nv_bfloat162*)&g_K2l[po + 2] = l23;
    float4 v1 = *(const float4*)&g_Pf[grow + 1536 + c4];
    float4 v2 = *(const float4*)&g_Pf[grow + 2048 + c4];
    split2(v1.x + v2.x, h01.x, l01.x); split2(v1.y + v2.y, h01.y, l01.y);
    split2(v1.z + v2.z, h23.x, l23.x); split2(v1.w + v2.w, h23.y, l23.y);
    *(__nv_bfloat162*)&g_Vmh[po]     = h01;
    *(__nv_bfloat162*)&g_Vmh[po + 2] = h23;
    *(__nv_bfloat162*)&g_Vml[po]     = l01;
    *(__nv_bfloat162*)&g_Vml[po + 2] = l23;
}

// ---------------- merged projection GEMM ----------------
// grid.x = 1024: [0,640) local CTAs (3-term, 2-stage), [640,1024) global (1-term, 3-stage)
__global__ __launch_bounds__(256, 2) void proj_all() {
    extern __shared__ char psm[];
    __nv_bfloat16* SB = (__nv_bfloat16*)psm;
    float* sbias = (float*)(psm + 81920);
    const int bx = blockIdx.x;
    const int tid = threadIdx.x, lane = tid & 31, warp = tid >> 5;
    const int wr = warp >> 1, wc = warp & 1;
    const int g = lane >> 2, tig = lane & 3;
    const int lr = tid >> 2, lch = tid & 3;

    float c[2][8][4];
#pragma unroll
    for (int mf = 0; mf < 2; mf++)
#pragma unroll
        for (int nf = 0; nf < 8; nf++)
#pragma unroll
            for (int i = 0; i < 4; i++) c[mf][nf][i] = 0.f;

    if (bx < 640) {
        // ----- local path: 3-term hi/lo, 2-stage pipeline -----
        const int bn = bx % 20, bm = bx / 20;
        if (tid < 128) sbias[tid] = g_bias[GC + bn * 128 + tid];

#define LP_AH(s) (SB + (s) * 20480)
#define LP_BH(s) (SB + (s) * 20480 + 5120)
#define LP_AL(s) (SB + (s) * 20480 + 10240)
#define LP_BL(s) (SB + (s) * 20480 + 15360)
#define LP_ISS(kt, s) {                                                        \
        int k0 = (kt) * 32;                                                    \
        size_t ga0 = (size_t)(bm * 128 + lr) * HID + k0 + lch * 8;             \
        size_t gb0 = (size_t)(GC + bn * 128 + lr) * HID + k0 + lch * 8;        \
        cp16(LP_AH(s) + lr * 40 + lch * 8,        g_Xh + ga0);                 \
        cp16(LP_AH(s) + (lr + 64) * 40 + lch * 8, g_Xh + ga0 + 64 * HID);      \
        cp16(LP_BH(s) + lr * 40 + lch * 8,        g_Wth + gb0);                \
        cp16(LP_BH(s) + (lr + 64) * 40 + lch * 8, g_Wth + gb0 + 64 * HID);     \
        cp16(LP_AL(s) + lr * 40 + lch * 8,        g_Xl + ga0);                 \
        cp16(LP_AL(s) + (lr + 64) * 40 + lch * 8, g_Xl + ga0 + 64 * HID);      \
        cp16(LP_BL(s) + lr * 40 + lch * 8,        g_Wtl + gb0);                \
        cp16(LP_BL(s) + (lr + 64) * 40 + lch * 8, g_Wtl + gb0 + 64 * HID); }

        LP_ISS(0, 0); asm volatile("cp.async.commit_group;");

        for (int kt = 0; kt < 32; kt++) {
            const int s = kt & 1;
            if (kt + 1 < 32) { LP_ISS(kt + 1, s ^ 1); }
            asm volatile("cp.async.commit_group;");
            asm volatile("cp.async.wait_group 1;");
            __syncthreads();

            __nv_bfloat16* Ah = LP_AH(s);
            __nv_bfloat16* Bh = LP_BH(s);
            __nv_bfloat16* Al = LP_AL(s);
            __nv_bfloat16* Bl = LP_BL(s);
            uint32_t ah[2][2][4], al[2][2][4];
#pragma unroll
            for (int mf = 0; mf < 2; mf++)
#pragma unroll
                for (int ks = 0; ks < 2; ks++) {
                    int row = wr * 32 + mf * 16 + (lane & 15);
                    int col = ks * 16 + (lane >> 4) * 8;
                    ldsm_x4(ah[mf][ks], cvta_s(&Ah[row * 40 + col]));
                    ldsm_x4(al[mf][ks], cvta_s(&Al[row * 40 + col]));
                }
#pragma unroll
            for (int nfp = 0; nfp < 4; nfp++) {
#pragma unroll
                for (int ks = 0; ks < 2; ks++) {
                    uint32_t bh4[4], bl4[4];
                    int row = wc * 64 + nfp * 16 + (lane & 15);
                    int col = ks * 16 + (lane >> 4) * 8;
                    ldsm_x4(bh4, cvta_s(&Bh[row * 40 + col]));
                    ldsm_x4(bl4, cvta_s(&Bl[row * 40 + col]));
#pragma unroll
                    for (int mf = 0; mf < 2; mf++) {
                        mma_bf16b(c[mf][2 * nfp],     ah[mf][ks], bh4[0], bh4[2]);
                        mma_bf16b(c[mf][2 * nfp],     al[mf][ks], bh4[0], bh4[2]);
                        mma_bf16b(c[mf][2 * nfp],     ah[mf][ks], bl4[0], bl4[2]);
                        mma_bf16b(c[mf][2 * nfp + 1], ah[mf][ks], bh4[1], bh4[3]);
                        mma_bf16b(c[mf][2 * nfp + 1], al[mf][ks], bh4[1], bh4[3]);
                        mma_bf16b(c[mf][2 * nfp + 1], ah[mf][ks], bl4[1], bl4[3]);
                    }
                }
            }
            __syncthreads();
        }

#pragma unroll
        for (int mf = 0; mf < 2; mf++)
#pragma unroll
            for (int nf = 0; nf < 8; nf++) {
                int lcol = wc * 64 + nf * 8 + 2 * tig;
                int fc = bn * 128 + lcol;
                int r0 = bm * 128 + wr * 32 + mf * 16 + g;
                g_Pf[(size_t)r0 * LC + fc]           = c[mf][nf][0] + sbias[lcol];
                g_Pf[(size_t)r0 * LC + fc + 1]       = c[mf][nf][1] + sbias[lcol + 1];
                g_Pf[(size_t)(r0 + 8) * LC + fc]     = c[mf][nf][2] + sbias[lcol];
                g_Pf[(size_t)(r0 + 8) * LC + fc + 1] = c[mf][nf][3] + sbias[lcol + 1];
            }
    } else {
        // ----- global path: 1-term, 3-stage pipeline -----
        const int y = bx - 640;
        const int bn = y % 12, bm = y / 12;
        if (tid < 128) sbias[tid] = g_bias[bn * 128 + tid];

#define GP_A(s) (SB + (s) * 5120)
#define GP_B(s) (SB + 15360 + (s) * 5120)
#define GP_ISS(kt, s) {                                                        \
        int k0 = (kt) * 32;                                                    \
        size_t ga0 = (size_t)(bm * 128 + lr) * HID + k0 + lch * 8;             \
        size_t gb0 = (size_t)(bn * 128 + lr) * HID + k0 + lch * 8;             \
        cp16(GP_A(s) + lr * 40 + lch * 8,        g_Xh + ga0);                  \
        cp16(GP_A(s) + (lr + 64) * 40 + lch * 8, g_Xh + ga0 + 64 * HID);       \
        cp16(GP_B(s) + lr * 40 + lch * 8,        g_Wth + gb0);                 \
        cp16(GP_B(s) + (lr + 64) * 40 + lch * 8, g_Wth + gb0 + 64 * HID); }

        GP_ISS(0, 0); asm volatile("cp.async.commit_group;");
        GP_ISS(1, 1); asm volatile("cp.async.commit_group;");

        for (int kt = 0; kt < 32; kt++) {
            const int s = kt % 3;
            asm volatile("cp.async.wait_group 1;");
            __syncthreads();
            if (kt + 2 < 32) { GP_ISS(kt + 2, (kt + 2) % 3); }
            asm volatile("cp.async.commit_group;");

            __nv_bfloat16* Ah = GP_A(s);
            __nv_bfloat16* Bh = GP_B(s);
            uint32_t ah[2][2][4];
#pragma unroll
            for (int mf = 0; mf < 2; mf++)
#pragma unroll
                for (int ks = 0; ks < 2; ks++) {
                    int row = wr * 32 + mf * 16 + (lane & 15);
                    int col = ks * 16 + (lane >> 4) * 8;
                    ldsm_x4(ah[mf][ks], cvta_s(&Ah[row * 40 + col]));
                }
#pragma unroll
            for (int nfp = 0; nfp < 4; nfp++) {
#pragma unroll
                for (int ks = 0; ks < 2; ks++) {
                    uint32_t b4[4];
                    int row = wc * 64 + nfp * 16 + (lane & 15);
                    int col = ks * 16 + (lane >> 4) * 8;
                    ldsm_x4(b4, cvta_s(&Bh[row * 40 + col]));
#pragma unroll
                    for (int mf = 0; mf < 2; mf++) {
                        mma_bf16b(c[mf][2 * nfp],     ah[mf][ks], b4[0], b4[2]);
                        mma_bf16b(c[mf][2 * nfp + 1], ah[mf][ks], b4[1], b4[3]);
                    }
                }
            }
        }

#pragma unroll
        for (int mf = 0; mf < 2; mf++)
#pragma unroll
            for (int nf = 0; nf < 8; nf++) {
                int lcol = wc * 64 + nf * 8 + 2 * tig;
                int gcol = bn * 128 + lcol;
                int r0 = bm * 128 + wr * 32 + mf * 16 + g;
                float v0 = c[mf][nf][0] + sbias[lcol];
                float v1 = c[mf][nf][1] + sbias[lcol + 1];
                float v2 = c[mf][nf][2] + sbias[lcol];
                float v3 = c[mf][nf][3] + sbias[lcol + 1];
                *(uint32_t*)&g_Pg[(size_t)r0 * GC + gcol]       = pack_bf16(v0, v1);
                *(uint32_t*)&g_Pg[(size_t)(r0 + 8) * GC + gcol] = pack_bf16(v2, v3);
            }
    }
}

// ---------------- M = lk1^T lk1 (fp32) ----------------
__global__ __launch_bounds__(256) void compute_M_part() {
    __shared__ float Ls[64 * 68];
    const int bh = blockIdx.x, b = bh >> 3, h = bh & 7;
    const int part = blockIdx.y;
    const int tid = threadIdx.x, e = tid & 63, d0 = tid >> 6;
    float acc[16];
#pragma unroll
    for (int i = 0; i < 16; i++) acc[i] = 0.f;
    const int colbase = 512 + h * 64;
    for (int t = 0; t < 4; t++) {
        const int s0 = (part * 4 + t) * 64;
        __syncthreads();
#pragma unroll
        for (int ch = 0; ch < 4; ch++) {
            int idx = tid + 256 * ch;
            int r = idx >> 4, c4 = (idx & 15) * 4;
            *(float4*)&Ls[r * 68 + c4] =
                *(const float4*)&g_Pf[(size_t)(b * SEQ + s0 + r) * LC + colbase + c4];
        }
        __syncthreads();
        for (int r = 0; r < 64; r++) {
            float le = Ls[r * 68 + e];
#pragma unroll
            for (int i = 0; i < 16; i++)
                acc[i] += Ls[r * 68 + d0 + 4 * i] * le;
        }
    }
#pragma unroll
    for (int i = 0; i < 16; i++)
        g_Mpart[((size_t)part * 16 + bh) * 4096 + (d0 + 4 * i) * 64 + e] = acc[i];
}

__global__ __launch_bounds__(256) void reduce_M() {
    const int t = blockIdx.x * 256 + threadIdx.x;
    const int bh = t >> 12, idx = t & 4095;
    float s = 0.f;
#pragma unroll
    for (int p = 0; p < 8; p++) s += g_Mpart[((size_t)p * 16 + bh) * 4096 + idx];
    g_M[(size_t)bh * 4096 + idx] = s;
}

// ---------------- LQ' = LQ @ M (fp32, in place) ----------------
__global__ __launch_bounds__(256) void lq_update() {
    __shared__ float Ms[64 * 65];
    __shared__ float Ls[64 * 68];
    const int rb = blockIdx.x, h = blockIdx.y;
    const int row0 = rb * 64, b = row0 >> 11, bh = b * 8 + h;
    const int tid = threadIdx.x;
    const int colbase = h * 64;
#pragma unroll
    for (int ch = 0; ch < 16; ch++) {
        int idx = tid + 256 * ch;
        Ms[(idx >> 6) * 65 + (idx & 63)] = g_M[(size_t)bh * 4096 + idx];
    }
#pragma unroll
    for (int ch = 0; ch < 4; ch++) {
        int idx = tid + 256 * ch;
        int r = idx >> 4, c4 = (idx & 15) * 4;
        *(float4*)&Ls[r * 68 + c4] =
            *(const float4*)&g_Pf[(size_t)(row0 + r) * LC + colbase + c4];
    }
    __syncthreads();
    const int e = tid & 63, r0 = tid >> 6;
    float acc[16];
#pragma unroll
    for (int i = 0; i < 16; i++) acc[i] = 0.f;
    for (int d = 0; d < 64; d++) {
        float mv = Ms[d * 65 + e];
#pragma unroll
        for (int i = 0; i < 16; i++)
            acc[i] += Ls[(r0 + 4 * i) * 68 + d] * mv;
    }
#pragma unroll
    for (int i = 0; i < 16; i++)
        g_Pf[(size_t)(row0 + r0 + 4 * i) * LC + colbase + e] = acc[i];
}

// ---------------- merged flash: [0,256) local, [256,512) global ----------------
__global__ __launch_bounds__(256, 2) void flash_all(const float* __restrict__ mask,
                                                    float* __restrict__ out) {
    extern __shared__ char fsm[];
    const int tid = threadIdx.x, lane = tid & 31, warp = tid >> 5;
    const int g = lane >> 2, tig = lane & 3;
    const int bx = blockIdx.x;
    const int lr = tid >> 2, lch = tid & 3;

    if (bx < 256) {
        // ===== local branch: bf16 3-term QK, 2-term PV, 2-stage pipeline =====
#define LF_KH(s) ((__nv_bfloat16*)(fsm + (s) * 36864))
#define LF_KL(s) ((__nv_bfloat16*)(fsm + (s) * 36864 + 9216))
#define LF_VH(s) ((__nv_bfloat16*)(fsm + (s) * 36864 + 18432))
#define LF_VL(s) ((__nv_bfloat16*)(fsm + (s) * 36864 + 27648))
        const int qb = bx & 15, by = bx >> 4;
        const int b = by >> 3, h = by & 7;
        const int rowbase = b * SEQ;

#define LF_ISS(kt, s) {                                                        \
        size_t go = (size_t)(rowbase + (kt) * 64 + lr) * 512 + h * 64 + lch * 16; \
        cp16(LF_KH(s) + lr * 72 + lch * 16,     &g_K2h[go]);                   \
        cp16(LF_KH(s) + lr * 72 + lch * 16 + 8, &g_K2h[go + 8]);               \
        cp16(LF_KL(s) + lr * 72 + lch * 16,     &g_K2l[go]);                   \
        cp16(LF_KL(s) + lr * 72 + lch * 16 + 8, &g_K2l[go + 8]);               \
        cp16(LF_VH(s) + lr * 72 + lch * 16,     &g_Vmh[go]);                   \
        cp16(LF_VH(s) + lr * 72 + lch * 16 + 8, &g_Vmh[go + 8]);               \
        cp16(LF_VL(s) + lr * 72 + lch * 16,     &g_Vml[go]);                   \
        cp16(LF_VL(s) + lr * 72 + lch * 16 + 8, &g_Vml[go + 8]); }

        uint32_t qh[4][4], ql[4][4];
        const int qr0 = rowbase + qb * 128 + warp * 16 + g;
        const float* P0 = &g_Pf[(size_t)qr0 * LC + h * 64];
        const float* P1 = &g_Pf[(size_t)(qr0 + 8) * LC + h * 64];
#pragma unroll
        for (int ks = 0; ks < 4; ks++) {
            int c0 = ks * 16 + 2 * tig;
            pack_hl(P0[c0],     P0[c0 + 1], qh[ks][0], ql[ks][0]);
            pack_hl(P1[c0],     P1[c0 + 1], qh[ks][1], ql[ks][1]);
            pack_hl(P0[c0 + 8], P0[c0 + 9], qh[ks][2], ql[ks][2]);
            pack_hl(P1[c0 + 8], P1[c0 + 9], qh[ks][3], ql[ks][3]);
        }

        LF_ISS(0, 0); asm volatile("cp.async.commit_group;");

        float of[8][4];
#pragma unroll
        for (int nf = 0; nf < 8; nf++)
#pragma unroll
            for (int i = 0; i < 4; i++) of[nf][i] = 0.f;
        float m0 = -1e30f, m1 = -1e30f, l0 = 0.f, l1 = 0.f;

        for (int kt = 0; kt < 32; kt++) {
            const int s = kt & 1;
            if (kt + 1 < 32) { LF_ISS(kt + 1, s ^ 1); }
            asm volatile("cp.async.commit_group;");
            asm volatile("cp.async.wait_group 1;");
            __syncthreads();

            __nv_bfloat16* Kh = LF_KH(s);
            __nv_bfloat16* Kl = LF_KL(s);
            __nv_bfloat16* Vh = LF_VH(s);
            __nv_bfloat16* Vl = LF_VL(s);

            float sf[8][4];
#pragma unroll
            for (int nfp = 0; nfp < 4; nfp++) {
#pragma unroll
                for (int i = 0; i < 4; i++) { sf[2*nfp][i] = 0.f; sf[2*nfp+1][i] = 0.f; }
#pragma unroll
                for (int ks = 0; ks < 4; ks++) {
                    uint32_t kh4[4], kl4[4];
                    int row = nfp * 16 + (lane & 15);
                    int col = ks * 16 + (lane >> 4) * 8;
                    ldsm_x4(kh4, cvta_s(&Kh[row * 72 + col]));
                    ldsm_x4(kl4, cvta_s(&Kl[row * 72 + col]));
                    mma_bf16b(sf[2 * nfp],     qh[ks], kh4[0], kh4[2]);
                    mma_bf16b(sf[2 * nfp],     ql[ks], kh4[0], kh4[2]);
                    mma_bf16b(sf[2 * nfp],     qh[ks], kl4[0], kl4[2]);
                    mma_bf16b(sf[2 * nfp + 1], qh[ks], kh4[1], kh4[3]);
                    mma_bf16b(sf[2 * nfp + 1], ql[ks], kh4[1], kh4[3]);
                    mma_bf16b(sf[2 * nfp + 1], qh[ks], kl4[1], kl4[3]);
                }
            }

            float mx0 = -1e30f, mx1 = -1e30f;
#pragma unroll
            for (int nf = 0; nf < 8; nf++) {
                sf[nf][0] *= 0.125f; sf[nf][1] *= 0.125f;
                sf[nf][2] *= 0.125f; sf[nf][3] *= 0.125f;
                mx0 = fmaxf(mx0, fmaxf(sf[nf][0], sf[nf][1]));
                mx1 = fmaxf(mx1, fmaxf(sf[nf][2], sf[nf][3]));
            }
            mx0 = fmaxf(mx0, __shfl_xor_sync(~0u, mx0, 1));
            mx0 = fmaxf(mx0, __shfl_xor_sync(~0u, mx0, 2));
            mx1 = fmaxf(mx1, __shfl_xor_sync(~0u, mx1, 1));
            mx1 = fmaxf(mx1, __shfl_xor_sync(~0u, mx1, 2));
            float mn0 = fmaxf(m0, mx0), mn1 = fmaxf(m1, mx1);
            float cr0 = __expf(m0 - mn0), cr1 = __expf(m1 - mn1);
            m0 = mn0; m1 = mn1;

            float ps0 = 0.f, ps1 = 0.f;
            uint32_t pah[4][4];
#pragma unroll
            for (int nf = 0; nf < 8; nf++) {
                float p0 = __expf(sf[nf][0] - mn0), p1 = __expf(sf[nf][1] - mn0);
                float p2 = __expf(sf[nf][2] - mn1), p3 = __expf(sf[nf][3] - mn1);
                ps0 += p0 + p1; ps1 += p2 + p3;
                int ks = nf >> 1;
                if (nf & 1) { pah[ks][2] = pack_bf16(p0, p1); pah[ks][3] = pack_bf16(p2, p3); }
                else        { pah[ks][0] = pack_bf16(p0, p1); pah[ks][1] = pack_bf16(p2, p3); }
            }
            ps0 += __shfl_xor_sync(~0u, ps0, 1); ps0 += __shfl_xor_sync(~0u, ps0, 2);
            ps1 += __shfl_xor_sync(~0u, ps1, 1); ps1 += __shfl_xor_sync(~0u, ps1, 2);
            l0 = l0 * cr0 + ps0; l1 = l1 * cr1 + ps1;
#pragma unroll
            for (int nf = 0; nf < 8; nf++) {
                of[nf][0] *= cr0; of[nf][1] *= cr0; of[nf][2] *= cr1; of[nf][3] *= cr1;
            }
#pragma unroll
            for (int nfp = 0; nfp < 4; nfp++)
#pragma unroll
                for (int ks = 0; ks < 4; ks++) {
                    uint32_t vh4[4], vl4[4];
                    int row = ks * 16 + (lane & 15);
                    int col = nfp * 16 + (lane >> 4) * 8;
                    ldsm_x4t(vh4, cvta_s(&Vh[row * 72 + col]));
                    ldsm_x4t(vl4, cvta_s(&Vl[row * 72 + col]));
                    mma_bf16b(of[2 * nfp],     pah[ks], vh4[0], vh4[1]);
                    mma_bf16b(of[2 * nfp],     pah[ks], vl4[0], vl4[1]);
                    mma_bf16b(of[2 * nfp + 1], pah[ks], vh4[2], vh4[3]);
                    mma_bf16b(of[2 * nfp + 1], pah[ks], vl4[2], vl4[3]);
                }
            __syncthreads();
        }

        const float inv0 = 1.f / l0, inv1 = 1.f / l1;
        const int r0 = rowbase + qb * 128 + warp * 16 + g;
#pragma unroll
        for (int nf = 0; nf < 8; nf++) {
            int col = (8 + h) * 64 + nf * 8 + 2 * tig;
            out[(size_t)r0 * HID + col]           = of[nf][0] * inv0;
            out[(size_t)r0 * HID + col + 1]       = of[nf][1] * inv0;
            out[(size_t)(r0 + 8) * HID + col]     = of[nf][2] * inv1;
            out[(size_t)(r0 + 8) * HID + col + 1] = of[nf][3] * inv1;
        }
    } else {
        // ===== global branch: bf16 1-term, 3-stage pipeline =====
        __nv_bfloat16* Qs = (__nv_bfloat16*)fsm;                 // 128*72
        float* maskS = (float*)(fsm + 18432);                    // 2048 floats
#define GF_K(s) ((__nv_bfloat16*)(fsm + 26624 + (s) * 18432))
#define GF_V(s) ((__nv_bfloat16*)(fsm + 26624 + (s) * 18432 + 9216))
        const int y = bx - 256;
        const int qb = y & 15, by = y >> 4;
        const int b = by >> 3, h = by & 7;
        const int qcol = h * 64, kcol = 512 + h * 64, vcol = 1024 + h * 64;
        const int rowbase = b * SEQ;

#define GF_ISS(kt, s) {                                                        \
        size_t grow = (size_t)(rowbase + (kt) * 64 + lr) * GC;                 \
        cp16(GF_K(s) + lr * 72 + lch * 16,     &g_Pg[grow + kcol + lch * 16]); \
        cp16(GF_K(s) + lr * 72 + lch * 16 + 8, &g_Pg[grow + kcol + lch * 16 + 8]); \
        cp16(GF_V(s) + lr * 72 + lch * 16,     &g_Pg[grow + vcol + lch * 16]); \
        cp16(GF_V(s) + lr * 72 + lch * 16 + 8, &g_Pg[grow + vcol + lch * 16 + 8]); }

#pragma unroll
        for (int i = 0; i < 8; i++) maskS[tid + 256 * i] = mask[b * SEQ + tid + 256 * i];
#pragma unroll
        for (int i = 0; i < 4; i++) {
            int idx = tid + 256 * i;
            int r = idx >> 3, ch = idx & 7;
            *(uint4*)&Qs[r * 72 + ch * 8] =
                *(const uint4*)&g_Pg[(size_t)(rowbase + qb * 128 + r) * GC + qcol + ch * 8];
        }
        GF_ISS(0, 0); asm volatile("cp.async.commit_group;");
        GF_ISS(1, 1); asm volatile("cp.async.commit_group;");
        __syncthreads();

        uint32_t qf[4][4];
#pragma unroll
        for (int ks = 0; ks < 4; ks++) {
            int row = warp * 16 + (lane & 15);
            int col = ks * 16 + (lane >> 4) * 8;
            ldsm_x4(qf[ks], cvta_s(&Qs[row * 72 + col]));
        }

        float of[8][4];
#pragma unroll
        for (int nf = 0; nf < 8; nf++)
#pragma unroll
            for (int i = 0; i < 4; i++) of[nf][i] = 0.f;
        float m0 = -1e30f, m1 = -1e30f, l0 = 0.f, l1 = 0.f;

        for (int kt = 0; kt < 32; kt++) {
            const int s = kt % 3;
            asm volatile("cp.async.wait_group 1;");
            __syncthreads();
            if (kt + 2 < 32) { GF_ISS(kt + 2, (kt + 2) % 3); }
            asm volatile("cp.async.commit_group;");

            __nv_bfloat16* Ks = GF_K(s);
            __nv_bfloat16* Vs = GF_V(s);

            float sf[8][4];
#pragma unroll
            for (int nfp = 0; nfp < 4; nfp++) {
#pragma unroll
                for (int i = 0; i < 4; i++) { sf[2*nfp][i] = 0.f; sf[2*nfp+1][i] = 0.f; }
#pragma unroll
                for (int ks = 0; ks < 4; ks++) {
                    uint32_t k4[4];
                    int row = nfp * 16 + (lane & 15);
                    int col = ks * 16 + (lane >> 4) * 8;
                    ldsm_x4(k4, cvta_s(&Ks[row * 72 + col]));
                    mma_bf16b(sf[2 * nfp],     qf[ks], k4[0], k4[2]);
                    mma_bf16b(sf[2 * nfp + 1], qf[ks], k4[1], k4[3]);
                }
            }

            float mx0 = -1e30f, mx1 = -1e30f;
#pragma unroll
            for (int nf = 0; nf < 8; nf++) {
                float a0 = maskS[kt * 64 + nf * 8 + 2 * tig];
                float a1 = maskS[kt * 64 + nf * 8 + 2 * tig + 1];
                sf[nf][0] = sf[nf][0] * 0.125f + a0;
                sf[nf][1] = sf[nf][1] * 0.125f + a1;
                sf[nf][2] = sf[nf][2] * 0.125f + a0;
                sf[nf][3] = sf[nf][3] * 0.125f + a1;
                mx0 = fmaxf(mx0, fmaxf(sf[nf][0], sf[nf][1]));
                mx1 = fmaxf(mx1, fmaxf(sf[nf][2], sf[nf][3]));
            }
            mx0 = fmaxf(mx0, __shfl_xor_sync(~0u, mx0, 1));
            mx0 = fmaxf(mx0, __shfl_xor_sync(~0u, mx0, 2));
            mx1 = fmaxf(mx1, __shfl_xor_sync(~0u, mx1, 1));
            mx1 = fmaxf(mx1, __shfl_xor_sync(~0u, mx1, 2));
            float mn0 = fmaxf(m0, mx0), mn1 = fmaxf(m1, mx1);
            float cr0 = __expf(m0 - mn0), cr1 = __expf(m1 - mn1);
            m0 = mn0; m1 = mn1;

            float ps0 = 0.f, ps1 = 0.f;
            uint32_t pa[4][4];
#pragma unroll
            for (int nf = 0; nf < 8; nf++) {
                float p0 = __expf(sf[nf][0] - mn0), p1 = __expf(sf[nf][1] - mn0);
                float p2 = __expf(sf[nf][2] - mn1), p3 = __expf(sf[nf][3] - mn1);
                ps0 += p0 + p1; ps1 += p2 + p3;
                int ks = nf >> 1;
                if (nf & 1) { pa[ks][2] = pack_bf16(p0, p1); pa[ks][3] = pack_bf16(p2, p3); }
                else        { pa[ks][0] = pack_bf16(p0, p1); pa[ks][1] = pack_bf16(p2, p3); }
            }
            ps0 += __shfl_xor_sync(~0u, ps0, 1); ps0 += __shfl_xor_sync(~0u, ps0, 2);
            ps1 += __shfl_xor_sync(~0u, ps1, 1); ps1 += __shfl_xor_sync(~0u, ps1, 2);
            l0 = l0 * cr0 + ps0; l1 = l1 * cr1 + ps1;
#pragma unroll
            for (int nf = 0; nf < 8; nf++) {
                of[nf][0] *= cr0; of[nf][1] *= cr0; of[nf][2] *= cr1; of[nf][3] *= cr1;
            }
#pragma unroll
            for (int nfp = 0; nfp < 4; nfp++)
#pragma unroll
                for (int ks = 0; ks < 4; ks++) {
                    uint32_t v4[4];
                    int row = ks * 16 + (lane & 15);
                    int col = nfp * 16 + (lane >> 4) * 8;
                    ldsm_x4t(v4, cvta_s(&Vs[row * 72 + col]));
                    mma_bf16b(of[2 * nfp],     pa[ks], v4[0], v4[1]);
                    mma_bf16b(of[2 * nfp + 1], pa[ks], v4[2], v4[3]);
                }
        }

        const float inv0 = 1.f / l0, inv1 = 1.f / l1;
        const int r0 = rowbase + qb * 128 + warp * 16 + g;
#pragma unroll
        for (int nf = 0; nf < 8; nf++) {
            int col = h * 64 + nf * 8 + 2 * tig;
            out[(size_t)r0 * HID + col]           = of[nf][0] * inv0;
            out[(size_t)r0 * HID + col + 1]       = of[nf][1] * inv0;
            out[(size_t)(r0 + 8) * HID + col]     = of[nf][2] * inv1;
            out[(size_t)(r0 + 8) * HID + col + 1] = of[nf][3] * inv1;
        }
    }
}

// ---------------------------------------------------------------------------
extern "C" void kernel_launch(void* const* d_in, const int* in_sizes, int n_in,
                              void* d_out, int out_size) {
    (void)in_sizes; (void)n_in; (void)out_size;
    const float* X    = (const float*)d_in[0];
    const float* mask = (const float*)d_in[1];
    ProjArgs pa;
    for (int i = 0; i < 8; i++) {
        pa.w[i] = (const float*)d_in[2 + 2 * i];
        pa.b[i] = (const float*)d_in[3 + 2 * i];
    }
    float* out = (float*)d_out;

    const int PASMEM = 81920 + 512;         // proj_all (union of both paths)
    const int FASMEM = 81920;               // flash_all (union: GF 81920, LF 73728)
    cudaFuncSetAttribute(proj_all, cudaFuncAttributeMaxDynamicSharedMemorySize, PASMEM);
    cudaFuncSetAttribute(flash_all, cudaFuncAttributeMaxDynamicSharedMemorySize, FASMEM);

    prep_all<<<8208, 256>>>(X, pa);
    proj_all<<<1024, 256, PASMEM>>>();
    compute_M_part<<<dim3(16, 8), 256>>>();
    reduce_M<<<256, 256>>>();
    lq_update<<<dim3(64, 8), 256>>>();
    prep_local<<<2048, 256>>>();
    flash_all<<<512, 256, FASMEM>>>(mask, out);
}

// round 11
// speedup vs baseline: 1.1620x; 1.0483x over previous
#include <cuda_runtime.h>
#include <cuda_bf16.h>
#include <cstdint>

#define SEQ 2048
#define NROWS 4096
#define HID 1024
#define GC 1536   // global proj cols: Q 0, K 512, V 1024
#define LC 2560   // local proj cols: LQ 0, LK1 512, LK2 1024, LV1 1536, LV2 2048

__device__ __nv_bfloat16 g_Xh[(size_t)NROWS * HID];
__device__ __nv_bfloat16 g_Xl[(size_t)NROWS * HID];
__device__ __nv_bfloat16 g_Wth[(size_t)4096 * HID];   // all 8 W, transposed [n][k]
__device__ __nv_bfloat16 g_Wtl[(size_t)4096 * HID];
__device__ float g_bias[4096];
__device__ __nv_bfloat16 g_Pg[(size_t)NROWS * GC];    // global projections bf16
__device__ float g_Pf[(size_t)NROWS * LC];            // local projections fp32
__device__ float g_Mpart[8 * 16 * 64 * 64];
__device__ float g_M[16 * 64 * 64];
__device__ __nv_bfloat16 g_K2h[(size_t)NROWS * 512];
__device__ __nv_bfloat16 g_K2l[(size_t)NROWS * 512];
__device__ __nv_bfloat16 g_Vmh[(size_t)NROWS * 512];
__device__ __nv_bfloat16 g_Vml[(size_t)NROWS * 512];

struct ProjArgs { const float* w[8]; const float* b[8]; };

// ---------------- helpers ----------------
__device__ __forceinline__ uint32_t cvta_s(const void* p) {
    return (uint32_t)__cvta_generic_to_shared(p);
}
__device__ __forceinline__ void cp16(void* smem, const void* gmem) {
    asm volatile("cp.async.cg.shared.global [%0], [%1], 16;"
                 :: "r"(cvta_s(smem)), "l"(gmem));
}
__device__ __forceinline__ void cp16s(uint32_t smem, const void* gmem) {
    asm volatile("cp.async.cg.shared.global [%0], [%1], 16;"
                 :: "r"(smem), "l"(gmem));
}
__device__ __forceinline__ void ldsm_x4(uint32_t r[4], uint32_t a) {
    asm volatile("ldmatrix.sync.aligned.m8n8.x4.shared.b16 {%0,%1,%2,%3}, [%4];"
                 : "=r"(r[0]), "=r"(r[1]), "=r"(r[2]), "=r"(r[3]) : "r"(a));
}
__device__ __forceinline__ void ldsm_x4t(uint32_t r[4], uint32_t a) {
    asm volatile("ldmatrix.sync.aligned.m8n8.x4.trans.shared.b16 {%0,%1,%2,%3}, [%4];"
                 : "=r"(r[0]), "=r"(r[1]), "=r"(r[2]), "=r"(r[3]) : "r"(a));
}
__device__ __forceinline__ void mma_bf16b(float c[4], const uint32_t a[4], uint32_t b0, uint32_t b1) {
    asm volatile("mma.sync.aligned.m16n8k16.row.col.f32.bf16.bf16.f32 "
                 "{%0,%1,%2,%3},{%4,%5,%6,%7},{%8,%9},{%0,%1,%2,%3};"
                 : "+f"(c[0]), "+f"(c[1]), "+f"(c[2]), "+f"(c[3])
                 : "r"(a[0]), "r"(a[1]), "r"(a[2]), "r"(a[3]), "r"(b0), "r"(b1));
}
__device__ __forceinline__ void split2(float x, __nv_bfloat16& h, __nv_bfloat16& l) {
    h = __float2bfloat16_rn(x);
    l = __float2bfloat16_rn(x - __bfloat162float(h));
}
__device__ __forceinline__ uint32_t pack_bf16(float a, float b) {
    __nv_bfloat162 t = __floats2bfloat162_rn(a, b);
    return *(uint32_t*)&t;
}
__device__ __forceinline__ void pack_hl(float a, float b, uint32_t& h, uint32_t& l) {
    __nv_bfloat162 hh = __floats2bfloat162_rn(a, b);
    __nv_bfloat162 ll = __floats2bfloat162_rn(a - __bfloat162float(hh.x),
                                              b - __bfloat162float(hh.y));
    h = *(uint32_t*)&hh; l = *(uint32_t*)&ll;
}

// bank-XOR swizzle for 64B rows of bf16 (4 x 16B chunks per row)
#define SW64(r, c16) ((r) * 64 + ((((c16)) ^ (((r) >> 1) & 3)) << 4))

// ---------------- merged prep: split_X | transW | bias_cat ----------------
__global__ void prep_all(const float* __restrict__ X, ProjArgs pa) {
    __shared__ float tile[32][33];
    const int bx = blockIdx.x;
    const int tid = threadIdx.x;
    if (bx < 4096) {
        int t = bx * 256 + tid;
        float4 v = *(const float4*)&X[(size_t)t * 4];
        __nv_bfloat16 h, l;
        split2(v.x, h, l); g_Xh[(size_t)t*4+0] = h; g_Xl[(size_t)t*4+0] = l;
        split2(v.y, h, l); g_Xh[(size_t)t*4+1] = h; g_Xl[(size_t)t*4+1] = l;
        split2(v.z, h, l); g_Xh[(size_t)t*4+2] = h; g_Xl[(size_t)t*4+2] = l;
        split2(v.w, h, l); g_Xh[(size_t)t*4+3] = h; g_Xl[(size_t)t*4+3] = l;
    } else if (bx < 8192) {
        const int y = bx - 4096;
        const int nb = y & 15, kb = (y >> 4) & 31, w = y >> 9;
        const float* __restrict__ W = pa.w[w];
        const int tx = tid & 31, ty0 = tid >> 5;
#pragma unroll
        for (int i = 0; i < 4; i++) {
            int ty = ty0 + 8 * i;
            tile[ty][tx] = W[(size_t)(kb * 32 + ty) * 512 + nb * 32 + tx];
        }
        __syncthreads();
#pragma unroll
        for (int i = 0; i < 4; i++) {
            int ty = ty0 + 8 * i;
            __nv_bfloat16 h, l; split2(tile[tx][ty], h, l);
            size_t o = (size_t)(w * 512 + nb * 32 + ty) * HID + kb * 32 + tx;
            g_Wth[o] = h; g_Wtl[o] = l;
        }
    } else {
        int t = (bx - 8192) * 256 + tid;
        g_bias[t] = pa.b[t >> 9][t & 511];
    }
}

// ---------------- projection GEMM: swizzled tiles, 3-stage, 2 CTAs/SM ----------------
// grid.x = 1024: [0,640) local (3-term), [640,1024) global (1-term)
// smem: [0,512) bias, stages at 1024. Plane = 128 rows x 32 bf16 (64B rows, SW64) = 8KB.
// local stage = 4 planes (Ah,Bh,Al,Bl) = 32KB; global stage = 2 planes = 16KB.
__global__ __launch_bounds__(256, 2) void proj_all() {
    extern __shared__ char psm[];
    float* sbias = (float*)psm;
    const uint32_t sbase = cvta_s(psm) + 1024;
    const int bx = blockIdx.x;
    const int tid = threadIdx.x, lane = tid & 31, warp = tid >> 5;
    const int wr = warp >> 1, wc = warp & 1;
    const int g = lane >> 2, tig = lane & 3;
    const bool isloc = bx < 640;
    const int bn = isloc ? (bx % 20) : ((bx - 640) % 12);
    const int bm = isloc ? (bx / 20) : ((bx - 640) / 12);
    const int nbase = isloc ? (GC + bn * 128) : (bn * 128);
    if (tid < 128) sbias[tid] = g_bias[nbase + tid];

    const int lr = tid >> 2, lc16 = tid & 3;     // each thread: rows lr, lr+64; chunk lc16

#define PLN(s, p) (sbase + (s) * 32768u + (p) * 8192u)
#define PLG(s, p) (sbase + (s) * 16384u + (p) * 8192u)
#define ISSL(kt, s) {                                                          \
        int k0 = (kt) * 32;                                                    \
        size_t ga = (size_t)(bm * 128 + lr) * HID + k0 + lc16 * 8;             \
        size_t gb = (size_t)(nbase + lr) * HID + k0 + lc16 * 8;                \
        uint32_t d0 = SW64(lr, lc16), d1 = SW64(lr + 64, lc16);                \
        cp16s(PLN(s,0) + d0, g_Xh + ga);                                       \
        cp16s(PLN(s,0) + d1, g_Xh + ga + 64 * HID);                            \
        cp16s(PLN(s,1) + d0, g_Wth + gb);                                      \
        cp16s(PLN(s,1) + d1, g_Wth + gb + 64 * HID);                           \
        cp16s(PLN(s,2) + d0, g_Xl + ga);                                       \
        cp16s(PLN(s,2) + d1, g_Xl + ga + 64 * HID);                            \
        cp16s(PLN(s,3) + d0, g_Wtl + gb);                                      \
        cp16s(PLN(s,3) + d1, g_Wtl + gb + 64 * HID); }
#define ISSG(kt, s) {                                                          \
        int k0 = (kt) * 32;                                                    \
        size_t ga = (size_t)(bm * 128 + lr) * HID + k0 + lc16 * 8;             \
        size_t gb = (size_t)(nbase + lr) * HID + k0 + lc16 * 8;                \
        uint32_t d0 = SW64(lr, lc16), d1 = SW64(lr + 64, lc16);                \
        cp16s(PLG(s,0) + d0, g_Xh + ga);                                       \
        cp16s(PLG(s,0) + d1, g_Xh + ga + 64 * HID);                            \
        cp16s(PLG(s,1) + d0, g_Wth + gb);                                      \
        cp16s(PLG(s,1) + d1, g_Wth + gb + 64 * HID); }

    float c[2][8][4];
#pragma unroll
    for (int mf = 0; mf < 2; mf++)
#pragma unroll
        for (int nf = 0; nf < 8; nf++)
#pragma unroll
            for (int i = 0; i < 4; i++) c[mf][nf][i] = 0.f;

    if (isloc) {
        ISSL(0, 0); asm volatile("cp.async.commit_group;");
        ISSL(1, 1); asm volatile("cp.async.commit_group;");
        for (int kt = 0; kt < 32; kt++) {
            const int s = kt % 3;
            asm volatile("cp.async.wait_group 1;");
            __syncthreads();
            if (kt + 2 < 32) { ISSL(kt + 2, (kt + 2) % 3); }
            asm volatile("cp.async.commit_group;");

            uint32_t ah[2][2][4], al[2][2][4];
#pragma unroll
            for (int mf = 0; mf < 2; mf++)
#pragma unroll
                for (int ks = 0; ks < 2; ks++) {
                    int row = wr * 32 + mf * 16 + (lane & 15);
                    int c16 = ks * 2 + (lane >> 4);
                    ldsm_x4(ah[mf][ks], PLN(s, 0) + SW64(row, c16));
                    ldsm_x4(al[mf][ks], PLN(s, 2) + SW64(row, c16));
                }
#pragma unroll
            for (int nfp = 0; nfp < 4; nfp++) {
#pragma unroll
                for (int ks = 0; ks < 2; ks++) {
                    uint32_t bh4[4], bl4[4];
                    int row = wc * 64 + nfp * 16 + (lane & 15);
                    int c16 = ks * 2 + (lane >> 4);
                    ldsm_x4(bh4, PLN(s, 1) + SW64(row, c16));
                    ldsm_x4(bl4, PLN(s, 3) + SW64(row, c16));
#pragma unroll
                    for (int mf = 0; mf < 2; mf++) {
                        mma_bf16b(c[mf][2 * nfp],     ah[mf][ks], bh4[0], bh4[2]);
                        mma_bf16b(c[mf][2 * nfp],     al[mf][ks], bh4[0], bh4[2]);
                        mma_bf16b(c[mf][2 * nfp],     ah[mf][ks], bl4[0], bl4[2]);
                        mma_bf16b(c[mf][2 * nfp + 1], ah[mf][ks], bh4[1], bh4[3]);
                        mma_bf16b(c[mf][2 * nfp + 1], al[mf][ks], bh4[1], bh4[3]);
                        mma_bf16b(c[mf][2 * nfp + 1], ah[mf][ks], bl4[1], bl4[3]);
                    }
                }
            }
        }
    } else {
        ISSG(0, 0); asm volatile("cp.async.commit_group;");
        ISSG(1, 1); asm volatile("cp.async.commit_group;");
        for (int kt = 0; kt < 32; kt++) {
            const int s = kt % 3;
            asm volatile("cp.async.wait_group 1;");
            __syncthreads();
            if (kt + 2 < 32) { ISSG(kt + 2, (kt + 2) % 3); }
            asm volatile("cp.async.commit_group;");

            uint32_t ah[2][2][4];
#pragma unroll
            for (int mf = 0; mf < 2; mf++)
#pragma unroll
                for (int ks = 0; ks < 2; ks++) {
                    int row = wr * 32 + mf * 16 + (lane & 15);
                    int c16 = ks * 2 + (lane >> 4);
                    ldsm_x4(ah[mf][ks], PLG(s, 0) + SW64(row, c16));
                }
#pragma unroll
            for (int nfp = 0; nfp < 4; nfp++) {
#pragma unroll
                for (int ks = 0; ks < 2; ks++) {
                    uint32_t b4[4];
                    int row = wc * 64 + nfp * 16 + (lane & 15);
                    int c16 = ks * 2 + (lane >> 4);
                    ldsm_x4(b4, PLG(s, 1) + SW64(row, c16));
#pragma unroll
                    for (int mf = 0; mf < 2; mf++) {
                        mma_bf16b(c[mf][2 * nfp],     ah[mf][ks], b4[0], b4[2]);
                        mma_bf16b(c[mf][2 * nfp + 1], ah[mf][ks], b4[1], b4[3]);
                    }
                }
            }
        }
    }

#pragma unroll
    for (int mf = 0; mf < 2; mf++)
#pragma unroll
        for (int nf = 0; nf < 8; nf++) {
            int lcol = wc * 64 + nf * 8 + 2 * tig;
            int r0 = bm * 128 + wr * 32 + mf * 16 + g;
            float v0 = c[mf][nf][0] + sbias[lcol];
            float v1 = c[mf][nf][1] + sbias[lcol + 1];
            float v2 = c[mf][nf][2] + sbias[lcol];
            float v3 = c[mf][nf][3] + sbias[lcol + 1];
            if (isloc) {
                int fc = bn * 128 + lcol;
                g_Pf[(size_t)r0 * LC + fc]           = v0;
                g_Pf[(size_t)r0 * LC + fc + 1]       = v1;
                g_Pf[(size_t)(r0 + 8) * LC + fc]     = v2;
                g_Pf[(size_t)(r0 + 8) * LC + fc + 1] = v3;
            } else {
                int gcol = bn * 128 + lcol;
                *(uint32_t*)&g_Pg[(size_t)r0 * GC + gcol]       = pack_bf16(v0, v1);
                *(uint32_t*)&g_Pg[(size_t)(r0 + 8) * GC + gcol] = pack_bf16(v2, v3);
            }
        }
}

// ---------------- merged: M partials [0,128) | prep_local [128,2176) ----------------
__global__ __launch_bounds__(256) void mpart_prep() {
    __shared__ float Ls[64 * 68];
    const int bx = blockIdx.x;
    const int tid = threadIdx.x;
    if (bx < 128) {
        const int bh = bx & 15, b = bh >> 3, h = bh & 7;
        const int part = bx >> 4;
        const int e = tid & 63, d0 = tid >> 6;
        float acc[16];
#pragma unroll
        for (int i = 0; i < 16; i++) acc[i] = 0.f;
        const int colbase = 512 + h * 64;
        for (int t = 0; t < 4; t++) {
            const int s0 = (part * 4 + t) * 64;
            __syncthreads();
#pragma unroll
            for (int ch = 0; ch < 4; ch++) {
                int idx = tid + 256 * ch;
                int r = idx >> 4, c4 = (idx & 15) * 4;
                *(float4*)&Ls[r * 68 + c4] =
                    *(const float4*)&g_Pf[(size_t)(b * SEQ + s0 + r) * LC + colbase + c4];
            }
            __syncthreads();
            for (int r = 0; r < 64; r++) {
                float le = Ls[r * 68 + e];
#pragma unroll
                for (int i = 0; i < 16; i++)
                    acc[i] += Ls[r * 68 + d0 + 4 * i] * le;
            }
        }
#pragma unroll
        for (int i = 0; i < 16; i++)
            g_Mpart[((size_t)part * 16 + bh) * 4096 + (d0 + 4 * i) * 64 + e] = acc[i];
    } else {
        int t = (bx - 128) * 256 + tid;
        int r = t >> 7, c4 = (t & 127) * 4;
        size_t grow = (size_t)r * LC;
        size_t po = (size_t)r * 512 + c4;
        float4 k = *(const float4*)&g_Pf[grow + 1024 + c4];
        __nv_bfloat162 h01, h23, l01, l23;
        split2(k.x, h01.x, l01.x); split2(k.y, h01.y, l01.y);
        split2(k.z, h23.x, l23.x); split2(k.w, h23.y, l23.y);
        *(__nv_bfloat162*)&g_K2h[po]     = h01;
        *(__nv_bfloat162*)&g_K2h[po + 2] = h23;
        *(__nv_bfloat162*)&g_K2l[po]     = l01;
        *(__nv_bfloat162*)&g_K2l[po + 2] = l23;
        float4 v1 = *(const float4*)&g_Pf[grow + 1536 + c4];
        float4 v2 = *(const float4*)&g_Pf[grow + 2048 + c4];
        split2(v1.x + v2.x, h01.x, l01.x); split2(v1.y + v2.y, h01.y, l01.y);
        split2(v1.z + v2.z, h23.x, l23.x); split2(v1.w + v2.w, h23.y, l23.y);
        *(__nv_bfloat162*)&g_Vmh[po]     = h01;
        *(__nv_bfloat162*)&g_Vmh[po + 2] = h23;
        *(__nv_bfloat162*)&g_Vml[po]     = l01;
        *(__nv_bfloat162*)&g_Vml[po + 2] = l23;
    }
}

__global__ __launch_bounds__(256) void reduce_M() {
    const int t = blockIdx.x * 256 + threadIdx.x;
    const int bh = t >> 12, idx = t & 4095;
    float s = 0.f;
#pragma unroll
    for (int p = 0; p < 8; p++) s += g_Mpart[((size_t)p * 16 + bh) * 4096 + idx];
    g_M[(size_t)bh * 4096 + idx] = s;
}

// ---------------- LQ' = LQ @ M (fp32, in place) ----------------
__global__ __launch_bounds__(256) void lq_update() {
    __shared__ float Ms[64 * 65];
    __shared__ float Ls[64 * 68];
    const int rb = blockIdx.x, h = blockIdx.y;
    const int row0 = rb * 64, b = row0 >> 11, bh = b * 8 + h;
    const int tid = threadIdx.x;
    const int colbase = h * 64;
#pragma unroll
    for (int ch = 0; ch < 16; ch++) {
        int idx = tid + 256 * ch;
        Ms[(idx >> 6) * 65 + (idx & 63)] = g_M[(size_t)bh * 4096 + idx];
    }
#pragma unroll
    for (int ch = 0; ch < 4; ch++) {
        int idx = tid + 256 * ch;
        int r = idx >> 4, c4 = (idx & 15) * 4;
        *(float4*)&Ls[r * 68 + c4] =
            *(const float4*)&g_Pf[(size_t)(row0 + r) * LC + colbase + c4];
    }
    __syncthreads();
    const int e = tid & 63, r0 = tid >> 6;
    float acc[16];
#pragma unroll
    for (int i = 0; i < 16; i++) acc[i] = 0.f;
    for (int d = 0; d < 64; d++) {
        float mv = Ms[d * 65 + e];
#pragma unroll
        for (int i = 0; i < 16; i++)
            acc[i] += Ls[(r0 + 4 * i) * 68 + d] * mv;
    }
#pragma unroll
    for (int i = 0; i < 16; i++)
        g_Pf[(size_t)(row0 + r0 + 4 * i) * LC + colbase + e] = acc[i];
}

// ---------------- merged flash: [0,256) local, [256,512) global ----------------
__global__ __launch_bounds__(256, 2) void flash_all(const float* __restrict__ mask,
                                                    float* __restrict__ out) {
    extern __shared__ char fsm[];
    const int tid = threadIdx.x, lane = tid & 31, warp = tid >> 5;
    const int g = lane >> 2, tig = lane & 3;
    const int bx = blockIdx.x;
    const int lr = tid >> 2, lch = tid & 3;

    if (bx < 256) {
#define LF_KH(s) ((__nv_bfloat16*)(fsm + (s) * 36864))
#define LF_KL(s) ((__nv_bfloat16*)(fsm + (s) * 36864 + 9216))
#define LF_VH(s) ((__nv_bfloat16*)(fsm + (s) * 36864 + 18432))
#define LF_VL(s) ((__nv_bfloat16*)(fsm + (s) * 36864 + 27648))
        const int qb = bx & 15, by = bx >> 4;
        const int b = by >> 3, h = by & 7;
        const int rowbase = b * SEQ;

#define LF_ISS(kt, s) {                                                        \
        size_t go = (size_t)(rowbase + (kt) * 64 + lr) * 512 + h * 64 + lch * 16; \
        cp16(LF_KH(s) + lr * 72 + lch * 16,     &g_K2h[go]);                   \
        cp16(LF_KH(s) + lr * 72 + lch * 16 + 8, &g_K2h[go + 8]);               \
        cp16(LF_KL(s) + lr * 72 + lch * 16,     &g_K2l[go]);                   \
        cp16(LF_KL(s) + lr * 72 + lch * 16 + 8, &g_K2l[go + 8]);               \
        cp16(LF_VH(s) + lr * 72 + lch * 16,     &g_Vmh[go]);                   \
        cp16(LF_VH(s) + lr * 72 + lch * 16 + 8, &g_Vmh[go + 8]);               \
        cp16(LF_VL(s) + lr * 72 + lch * 16,     &g_Vml[go]);                   \
        cp16(LF_VL(s) + lr * 72 + lch * 16 + 8, &g_Vml[go + 8]); }

        uint32_t qh[4][4], ql[4][4];
        const int qr0 = rowbase + qb * 128 + warp * 16 + g;
        const float* P0 = &g_Pf[(size_t)qr0 * LC + h * 64];
        const float* P1 = &g_Pf[(size_t)(qr0 + 8) * LC + h * 64];
#pragma unroll
        for (int ks = 0; ks < 4; ks++) {
            int c0 = ks * 16 + 2 * tig;
            pack_hl(P0[c0],     P0[c0 + 1], qh[ks][0], ql[ks][0]);
            pack_hl(P1[c0],     P1[c0 + 1], qh[ks][1], ql[ks][1]);
            pack_hl(P0[c0 + 8], P0[c0 + 9], qh[ks][2], ql[ks][2]);
            pack_hl(P1[c0 + 8], P1[c0 + 9], qh[ks][3], ql[ks][3]);
        }

        LF_ISS(0, 0); asm volatile("cp.async.commit_group;");

        float of[8][4];
#pragma unroll
        for (int nf = 0; nf < 8; nf++)
#pragma unroll
            for (int i = 0; i < 4; i++) of[nf][i] = 0.f;
        float m0 = -1e30f, m1 = -1e30f, l0 = 0.f, l1 = 0.f;

        for (int kt = 0; kt < 32; kt++) {
            const int s = kt & 1;
            if (kt + 1 < 32) { LF_ISS(kt + 1, s ^ 1); }
            asm volatile("cp.async.commit_group;");
            asm volatile("cp.async.wait_group 1;");
            __syncthreads();

            __nv_bfloat16* Kh = LF_KH(s);
            __nv_bfloat16* Kl = LF_KL(s);
            __nv_bfloat16* Vh = LF_VH(s);
            __nv_bfloat16* Vl = LF_VL(s);

            float sf[8][4];
#pragma unroll
            for (int nfp = 0; nfp < 4; nfp++) {
#pragma unroll
                for (int i = 0; i < 4; i++) { sf[2*nfp][i] = 0.f; sf[2*nfp+1][i] = 0.f; }
#pragma unroll
                for (int ks = 0; ks < 4; ks++) {
                    uint32_t kh4[4], kl4[4];
                    int row = nfp * 16 + (lane & 15);
                    int col = ks * 16 + (lane >> 4) * 8;
                    ldsm_x4(kh4, cvta_s(&Kh[row * 72 + col]));
                    ldsm_x4(kl4, cvta_s(&Kl[row * 72 + col]));
                    mma_bf16b(sf[2 * nfp],     qh[ks], kh4[0], kh4[2]);
                    mma_bf16b(sf[2 * nfp],     ql[ks], kh4[0], kh4[2]);
                    mma_bf16b(sf[2 * nfp],     qh[ks], kl4[0], kl4[2]);
                    mma_bf16b(sf[2 * nfp + 1], qh[ks], kh4[1], kh4[3]);
                    mma_bf16b(sf[2 * nfp + 1], ql[ks], kh4[1], kh4[3]);
                    mma_bf16b(sf[2 * nfp + 1], qh[ks], kl4[1], kl4[3]);
                }
            }

            float mx0 = -1e30f, mx1 = -1e30f;
#pragma unroll
            for (int nf = 0; nf < 8; nf++) {
                sf[nf][0] *= 0.125f; sf[nf][1] *= 0.125f;
                sf[nf][2] *= 0.125f; sf[nf][3] *= 0.125f;
                mx0 = fmaxf(mx0, fmaxf(sf[nf][0], sf[nf][1]));
                mx1 = fmaxf(mx1, fmaxf(sf[nf][2], sf[nf][3]));
            }
            mx0 = fmaxf(mx0, __shfl_xor_sync(~0u, mx0, 1));
            mx0 = fmaxf(mx0, __shfl_xor_sync(~0u, mx0, 2));
            mx1 = fmaxf(mx1, __shfl_xor_sync(~0u, mx1, 1));
            mx1 = fmaxf(mx1, __shfl_xor_sync(~0u, mx1, 2));
            float mn0 = fmaxf(m0, mx0), mn1 = fmaxf(m1, mx1);
            float cr0 = __expf(m0 - mn0), cr1 = __expf(m1 - mn1);
            m0 = mn0; m1 = mn1;

            float ps0 = 0.f, ps1 = 0.f;
            uint32_t pah[4][4];
#pragma unroll
            for (int nf = 0; nf < 8; nf++) {
                float p0 = __expf(sf[nf][0] - mn0), p1 = __expf(sf[nf][1] - mn0);
                float p2 = __expf(sf[nf][2] - mn1), p3 = __expf(sf[nf][3] - mn1);
                ps0 += p0 + p1; ps1 += p2 + p3;
                int ks = nf >> 1;
                if (nf & 1) { pah[ks][2] = pack_bf16(p0, p1); pah[ks][3] = pack_bf16(p2, p3); }
                else        { pah[ks][0] = pack_bf16(p0, p1); pah[ks][1] = pack_bf16(p2, p3); }
            }
            ps0 += __shfl_xor_sync(~0u, ps0, 1); ps0 += __shfl_xor_sync(~0u, ps0, 2);
            ps1 += __shfl_xor_sync(~0u, ps1, 1); ps1 += __shfl_xor_sync(~0u, ps1, 2);
            l0 = l0 * cr0 + ps0; l1 = l1 * cr1 + ps1;
#pragma unroll
            for (int nf = 0; nf < 8; nf++) {
                of[nf][0] *= cr0; of[nf][1] *= cr0; of[nf][2] *= cr1; of[nf][3] *= cr1;
            }
#pragma unroll
            for (int nfp = 0; nfp < 4; nfp++)
#pragma unroll
                for (int ks = 0; ks < 4; ks++) {
                    uint32_t vh4[4], vl4[4];
                    int row = ks * 16 + (lane & 15);
                    int col = nfp * 16 + (lane >> 4) * 8;
                    ldsm_x4t(vh4, cvta_s(&Vh[row * 72 + col]));
                    ldsm_x4t(vl4, cvta_s(&Vl[row * 72 + col]));
                    mma_bf16b(of[2 * nfp],     pah[ks], vh4[0], vh4[1]);
                    mma_bf16b(of[2 * nfp],     pah[ks], vl4[0], vl4[1]);
                    mma_bf16b(of[2 * nfp + 1], pah[ks], vh4[2], vh4[3]);
                    mma_bf16b(of[2 * nfp + 1], pah[ks], vl4[2], vl4[3]);
                }
            __syncthreads();
        }

        const float inv0 = 1.f / l0, inv1 = 1.f / l1;
        const int r0 = rowbase + qb * 128 + warp * 16 + g;
#pragma unroll
        for (int nf = 0; nf < 8; nf++) {
            int col = (8 + h) * 64 + nf * 8 + 2 * tig;
            out[(size_t)r0 * HID + col]           = of[nf][0] * inv0;
            out[(size_t)r0 * HID + col + 1]       = of[nf][1] * inv0;
            out[(size_t)(r0 + 8) * HID + col]     = of[nf][2] * inv1;
            out[(size_t)(r0 + 8) * HID + col + 1] = of[nf][3] * inv1;
        }
    } else {
        __nv_bfloat16* Qs = (__nv_bfloat16*)fsm;
        float* maskS = (float*)(fsm + 18432);
#define GF_K(s) ((__nv_bfloat16*)(fsm + 26624 + (s) * 18432))
#define GF_V(s) ((__nv_bfloat16*)(fsm + 26624 + (s) * 18432 + 9216))
        const int y = bx - 256;
        const int qb = y & 15, by = y >> 4;
        const int b = by >> 3, h = by & 7;
        const int qcol = h * 64, kcol = 512 + h * 64, vcol = 1024 + h * 64;
        const int rowbase = b * SEQ;

#define GF_ISS(kt, s) {                                                        \
        size_t grow = (size_t)(rowbase + (kt) * 64 + lr) * GC;                 \
        cp16(GF_K(s) + lr * 72 + lch * 16,     &g_Pg[grow + kcol + lch * 16]); \
        cp16(GF_K(s) + lr * 72 + lch * 16 + 8, &g_Pg[grow + kcol + lch * 16 + 8]); \
        cp16(GF_V(s) + lr * 72 + lch * 16,     &g_Pg[grow + vcol + lch * 16]); \
        cp16(GF_V(s) + lr * 72 + lch * 16 + 8, &g_Pg[grow + vcol + lch * 16 + 8]); }

#pragma unroll
        for (int i = 0; i < 8; i++) maskS[tid + 256 * i] = mask[b * SEQ + tid + 256 * i];
#pragma unroll
        for (int i = 0; i < 4; i++) {
            int idx = tid + 256 * i;
            int r = idx >> 3, ch = idx & 7;
            *(uint4*)&Qs[r * 72 + ch * 8] =
                *(const uint4*)&g_Pg[(size_t)(rowbase + qb * 128 + r) * GC + qcol + ch * 8];
        }
        GF_ISS(0, 0); asm volatile("cp.async.commit_group;");
        GF_ISS(1, 1); asm volatile("cp.async.commit_group;");
        __syncthreads();

        uint32_t qf[4][4];
#pragma unroll
        for (int ks = 0; ks < 4; ks++) {
            int row = warp * 16 + (lane & 15);
            int col = ks * 16 + (lane >> 4) * 8;
            ldsm_x4(qf[ks], cvta_s(&Qs[row * 72 + col]));
        }

        float of[8][4];
#pragma unroll
        for (int nf = 0; nf < 8; nf++)
#pragma unroll
            for (int i = 0; i < 4; i++) of[nf][i] = 0.f;
        float m0 = -1e30f, m1 = -1e30f, l0 = 0.f, l1 = 0.f;

        for (int kt = 0; kt < 32; kt++) {
            const int s = kt % 3;
            asm volatile("cp.async.wait_group 1;");
            __syncthreads();
            if (kt + 2 < 32) { GF_ISS(kt + 2, (kt + 2) % 3); }
            asm volatile("cp.async.commit_group;");

            __nv_bfloat16* Ks = GF_K(s);
            __nv_bfloat16* Vs = GF_V(s);

            float sf[8][4];
#pragma unroll
            for (int nfp = 0; nfp < 4; nfp++) {
#pragma unroll
                for (int i = 0; i < 4; i++) { sf[2*nfp][i] = 0.f; sf[2*nfp+1][i] = 0.f; }
#pragma unroll
                for (int ks = 0; ks < 4; ks++) {
                    uint32_t k4[4];
                    int row = nfp * 16 + (lane & 15);
                    int col = ks * 16 + (lane >> 4) * 8;
                    ldsm_x4(k4, cvta_s(&Ks[row * 72 + col]));
                    mma_bf16b(sf[2 * nfp],     qf[ks], k4[0], k4[2]);
                    mma_bf16b(sf[2 * nfp + 1], qf[ks], k4[1], k4[3]);
                }
            }

            float mx0 = -1e30f, mx1 = -1e30f;
#pragma unroll
            for (int nf = 0; nf < 8; nf++) {
                float a0 = maskS[kt * 64 + nf * 8 + 2 * tig];
                float a1 = maskS[kt * 64 + nf * 8 + 2 * tig + 1];
                sf[nf][0] = sf[nf][0] * 0.125f + a0;
                sf[nf][1] = sf[nf][1] * 0.125f + a1;
                sf[nf][2] = sf[nf][2] * 0.125f + a0;
                sf[nf][3] = sf[nf][3] * 0.125f + a1;
                mx0 = fmaxf(mx0, fmaxf(sf[nf][0], sf[nf][1]));
                mx1 = fmaxf(mx1, fmaxf(sf[nf][2], sf[nf][3]));
            }
            mx0 = fmaxf(mx0, __shfl_xor_sync(~0u, mx0, 1));
            mx0 = fmaxf(mx0, __shfl_xor_sync(~0u, mx0, 2));
            mx1 = fmaxf(mx1, __shfl_xor_sync(~0u, mx1, 1));
            mx1 = fmaxf(mx1, __shfl_xor_sync(~0u, mx1, 2));
            float mn0 = fmaxf(m0, mx0), mn1 = fmaxf(m1, mx1);
            float cr0 = __expf(m0 - mn0), cr1 = __expf(m1 - mn1);
            m0 = mn0; m1 = mn1;

            float ps0 = 0.f, ps1 = 0.f;
            uint32_t pa[4][4];
#pragma unroll
            for (int nf = 0; nf < 8; nf++) {
                float p0 = __expf(sf[nf][0] - mn0), p1 = __expf(sf[nf][1] - mn0);
                float p2 = __expf(sf[nf][2] - mn1), p3 = __expf(sf[nf][3] - mn1);
                ps0 += p0 + p1; ps1 += p2 + p3;
                int ks = nf >> 1;
                if (nf & 1) { pa[ks][2] = pack_bf16(p0, p1); pa[ks][3] = pack_bf16(p2, p3); }
                else        { pa[ks][0] = pack_bf16(p0, p1); pa[ks][1] = pack_bf16(p2, p3); }
            }
            ps0 += __shfl_xor_sync(~0u, ps0, 1); ps0 += __shfl_xor_sync(~0u, ps0, 2);
            ps1 += __shfl_xor_sync(~0u, ps1, 1); ps1 += __shfl_xor_sync(~0u, ps1, 2);
            l0 = l0 * cr0 + ps0; l1 = l1 * cr1 + ps1;
#pragma unroll
            for (int nf = 0; nf < 8; nf++) {
                of[nf][0] *= cr0; of[nf][1] *= cr0; of[nf][2] *= cr1; of[nf][3] *= cr1;
            }
#pragma unroll
            for (int nfp = 0; nfp < 4; nfp++)
#pragma unroll
                for (int ks = 0; ks < 4; ks++) {
                    uint32_t v4[4];
                    int row = ks * 16 + (lane & 15);
                    int col = nfp * 16 + (lane >> 4) * 8;
                    ldsm_x4t(v4, cvta_s(&Vs[row * 72 + col]));
                    mma_bf16b(of[2 * nfp],     pa[ks], v4[0], v4[1]);
                    mma_bf16b(of[2 * nfp + 1], pa[ks], v4[2], v4[3]);
                }
        }

        const float inv0 = 1.f / l0, inv1 = 1.f / l1;
        const int r0 = rowbase + qb * 128 + warp * 16 + g;
#pragma unroll
        for (int nf = 0; nf < 8; nf++) {
            int col = h * 64 + nf * 8 + 2 * tig;
            out[(size_t)r0 * HID + col]           = of[nf][0] * inv0;
            out[(size_t)r0 * HID + col + 1]       = of[nf][1] * inv0;
            out[(size_t)(r0 + 8) * HID + col]     = of[nf][2] * inv1;
            out[(size_t)(r0 + 8) * HID + col + 1] = of[nf][3] * inv1;
        }
    }
}

// ---------------------------------------------------------------------------
extern "C" void kernel_launch(void* const* d_in, const int* in_sizes, int n_in,
                              void* d_out, int out_size) {
    (void)in_sizes; (void)n_in; (void)out_size;
    const float* X    = (const float*)d_in[0];
    const float* mask = (const float*)d_in[1];
    ProjArgs pa;
    for (int i = 0; i < 8; i++) {
        pa.w[i] = (const float*)d_in[2 + 2 * i];
        pa.b[i] = (const float*)d_in[3 + 2 * i];
    }
    float* out = (float*)d_out;

    const int PASMEM = 1024 + 3 * 32768;    // 99328 (local path union)
    const int FASMEM = 81920;
    cudaFuncSetAttribute(proj_all, cudaFuncAttributeMaxDynamicSharedMemorySize, PASMEM);
    cudaFuncSetAttribute(flash_all, cudaFuncAttributeMaxDynamicSharedMemorySize, FASMEM);

    prep_all<<<8208, 256>>>(X, pa);
    proj_all<<<1024, 256, PASMEM>>>();
    mpart_prep<<<2176, 256>>>();
    reduce_M<<<256, 256>>>();
    lq_update<<<dim3(64, 8), 256>>>();
    flash_all<<<512, 256, FASMEM>>>(mask, out);
}